// round 13
// baseline (speedup 1.0000x reference)
#include <cuda_runtime.h>
#include <cuda_fp16.h>

// ---------------- fixed problem capacities (dataset is fixed) ----------------
#define NMAX 100000
#define EMAX 3200000
#define HDIM 64
#define ODIM 32
#define FDIM 128
#define XSTR 65    // padded fp32 [k][n] stride (gemm2)
#define HPAD 68    // padded half2/uint stride (=136 halves) for tensor gemm smem

// ---------------- device scratch (no allocations allowed) ----------------
__device__ int   g_is32;                              // 1 if edge indices are int32
__device__ int   g_ecnt[NMAX];                        // in-degree (no self loop)
__device__ int   g_ptr[NMAX + 1];                     // CSR offsets
__device__ unsigned long long g_scanstate[128];       // lookback: (flag<<32)|sum
__device__ float g_dinv[NMAX];                        // 1/sqrt(deg+1)
__device__ __align__(16) int     g_rank[EMAX];        // per-edge rank within dst
__device__ __align__(16) int     g_rows[EMAX];        // CSR adjacency: src per slot
__device__ __align__(16) __half2 g_s1h[NMAX * 32];    // fp16 dinv*(x@W1): 64 vals/node
__device__ __align__(16) __half2 g_z1h[NMAX * 32];    // fp16 relu layer-1 output
__device__ __align__(16) __half  g_s2h[NMAX * ODIM];  // fp16 dinv*(z1@W2): 32 vals/node
__device__ __align__(16) float   g_z2[NMAX * ODIM];   // layer-2 output (fp32)

__device__ __forceinline__ int edge_at(const void* p, long long j, int is32) {
    if (is32) return ((const int*)p)[j];
    return (int)((const long long*)p)[j];
}
__device__ __forceinline__ unsigned int pack_h2(float a, float b) {
    __half2 h = __floats2half2_rn(a, b);
    return *reinterpret_cast<unsigned int*>(&h);
}

// ---------------- prep: dtype detect + zero counters/flags ----------------
__global__ void k_prep(const void* ei, int E, int N) {
    int i = blockIdx.x * blockDim.x + threadIdx.x;
    if (i < N) g_ecnt[i] = 0;
    if (i < 128) g_scanstate[i] = 0ull;
    if (blockIdx.x == 0) {
        __shared__ int bad;
        if (threadIdx.x == 0) bad = 0;
        __syncthreads();
        int n = (2 * E < 256) ? 2 * E : 256;
        if (threadIdx.x < n) {
            long long v = ((const long long*)ei)[threadIdx.x];
            if (v < 0 || v >= NMAX) atomicOr(&bad, 1);
        }
        __syncthreads();
        if (threadIdx.x == 0) g_is32 = bad;
    }
}

// ------- count: 4 edges/thread; also records per-edge rank within its dst -------
__global__ void k_count(const void* __restrict__ ei, int E) {
    int q = blockIdx.x * blockDim.x + threadIdx.x;
    int e0 = q * 4;
    if (e0 >= E) return;
    int is32 = g_is32;
    if (e0 + 4 <= E) {
        int4 c;
        if (is32) {
            c = *(const int4*)((const int*)ei + E + e0);
        } else {
            const longlong2* p = (const longlong2*)((const long long*)ei + E + e0);
            longlong2 a = p[0], b = p[1];
            c = make_int4((int)a.x, (int)a.y, (int)b.x, (int)b.y);
        }
        int4 rk;
        rk.x = atomicAdd(&g_ecnt[c.x], 1);
        rk.y = atomicAdd(&g_ecnt[c.y], 1);
        rk.z = atomicAdd(&g_ecnt[c.z], 1);
        rk.w = atomicAdd(&g_ecnt[c.w], 1);
        *(int4*)(g_rank + e0) = rk;
    } else {
        for (int e = e0; e < E; e++) {
            int cc = edge_at(ei, (long long)E + e, is32);
            g_rank[e] = atomicAdd(&g_ecnt[cc], 1);
        }
    }
}

// ---- single-pass exclusive scan: warp scan + warp-parallel decoupled lookback ----
__global__ void k_scan(int N, int E) {
    __shared__ int wsum[32];
    __shared__ int s_prefix;
    int t = threadIdx.x, b = blockIdx.x;
    int lane = t & 31, wid = t >> 5;
    int i = b * 1024 + t;
    int v = (i < N) ? g_ecnt[i] : 0;

    int s = v;
#pragma unroll
    for (int o = 1; o < 32; o <<= 1) {
        int y = __shfl_up_sync(0xffffffffu, s, o);
        if (lane >= o) s += y;
    }
    if (lane == 31) wsum[wid] = s;
    __syncthreads();
    if (wid == 0) {
        int ws = wsum[lane];
#pragma unroll
        for (int o = 1; o < 32; o <<= 1) {
            int y = __shfl_up_sync(0xffffffffu, ws, o);
            if (lane >= o) ws += y;
        }
        wsum[lane] = ws;
    }
    __syncthreads();
    int incl = s + (wid ? wsum[wid - 1] : 0);
    int btotal = wsum[31];

    if (wid == 0) {
        if (b == 0) {
            if (lane == 0) {
                atomicExch(&g_scanstate[0], (2ull << 32) | (unsigned int)btotal);
                s_prefix = 0;
            }
        } else {
            if (lane == 0)
                atomicExch(&g_scanstate[b], (1ull << 32) | (unsigned int)btotal);
            __syncwarp();
            long long pref = 0;
            int base = b;
            while (true) {
                int idx = base - 32 + lane;
                bool valid = idx >= 0;
                unsigned long long st = 0;
                if (valid) {
                    do { st = atomicAdd(&g_scanstate[idx], 0ull); } while ((st >> 32) == 0);
                }
                unsigned m = __ballot_sync(0xffffffffu, valid && (st >> 32) == 2ull);
                int cut = m ? (31 - __clz(m)) : 32;
                bool contrib = valid && (cut == 32 || lane >= cut);
                long long c = contrib ? (long long)(st & 0xffffffffull) : 0;
#pragma unroll
                for (int o = 16; o; o >>= 1) c += __shfl_xor_sync(0xffffffffu, c, o);
                pref += c;
                if (cut != 32) break;
                base -= 32;
            }
            if (lane == 0) {
                atomicExch(&g_scanstate[b],
                           (2ull << 32) | (unsigned int)(pref + (long long)btotal));
                s_prefix = (int)pref;
            }
        }
    }
    __syncthreads();
    int p = s_prefix + incl - v;
    if (i < N) {
        g_ptr[i] = p;
        g_dinv[i] = rsqrtf((float)(g_ecnt[i] + 1));
    }
    if (i == 0) g_ptr[N] = E;
}

// ------- scatter (atomic-free fill): g_rows[ptr[c]+rank] = r -------
__global__ void k_scatter(const void* __restrict__ ei, int E) {
    int q = blockIdx.x * blockDim.x + threadIdx.x;
    int e0 = q * 4;
    if (e0 >= E) return;
    int is32 = g_is32;
    if (e0 + 4 <= E) {
        int4 r, c;
        if (is32) {
            r = *(const int4*)((const int*)ei + e0);
            c = *(const int4*)((const int*)ei + E + e0);
        } else {
            const longlong2* rp = (const longlong2*)((const long long*)ei + e0);
            const longlong2* cp = (const longlong2*)((const long long*)ei + E + e0);
            longlong2 ra = rp[0], rb = rp[1], ca = cp[0], cb = cp[1];
            r = make_int4((int)ra.x, (int)ra.y, (int)rb.x, (int)rb.y);
            c = make_int4((int)ca.x, (int)ca.y, (int)cb.x, (int)cb.y);
        }
        int4 rk = *(const int4*)(g_rank + e0);
        g_rows[g_ptr[c.x] + rk.x] = r.x;
        g_rows[g_ptr[c.y] + rk.y] = r.y;
        g_rows[g_ptr[c.z] + rk.z] = r.z;
        g_rows[g_ptr[c.w] + rk.w] = r.w;
    } else {
        for (int e = e0; e < E; e++) {
            int rr = edge_at(ei, e, is32);
            int cc = edge_at(ei, (long long)E + e, is32);
            g_rows[g_ptr[cc] + g_rank[e]] = rr;
        }
    }
}

// ---------------- GEMM1 (tensor cores): s1h_raw = fp16( x @ W1 ) ----------------
__global__ __launch_bounds__(256) void k_gemm1(const float* __restrict__ x,
                                               const float* __restrict__ W1, int N) {
    extern __shared__ unsigned int smu[];
    unsigned int* xh = smu;
    unsigned int* wh = smu + 128 * HPAD;
    __half* whh = (__half*)wh;
    int t = threadIdx.x;

    for (int i = t; i < FDIM * HDIM; i += 256) {
        int k = i >> 6, n = i & 63;
        whh[n * (2 * HPAD) + k] = __float2half_rn(W1[i]);
    }
    int node0 = blockIdx.x * 128;
    const float4* x4 = (const float4*)x;
    for (int i = t; i < 128 * 32; i += 256) {
        int nd = i >> 5, kq = i & 31;
        int gn = node0 + nd;
        float4 v = (gn < N) ? x4[(size_t)gn * 32 + kq] : make_float4(0.f, 0.f, 0.f, 0.f);
        xh[nd * HPAD + kq * 2]     = pack_h2(v.x, v.y);
        xh[nd * HPAD + kq * 2 + 1] = pack_h2(v.z, v.w);
    }
    __syncthreads();

    int wid = t >> 5, lane = t & 31;
    int g = lane >> 2, tq = lane & 3;
    int nodeW = wid * 16;

    unsigned int A[8][4];
#pragma unroll
    for (int ks = 0; ks < 8; ks++) {
        int base0 = (nodeW + g) * HPAD + ks * 8 + tq;
        int base1 = (nodeW + g + 8) * HPAD + ks * 8 + tq;
        A[ks][0] = xh[base0];
        A[ks][1] = xh[base1];
        A[ks][2] = xh[base0 + 4];
        A[ks][3] = xh[base1 + 4];
    }

    float acc[8][4];
#pragma unroll
    for (int nt = 0; nt < 8; nt++)
#pragma unroll
        for (int j = 0; j < 4; j++) acc[nt][j] = 0.f;

#pragma unroll
    for (int nt = 0; nt < 8; nt++) {
        int brow = (nt * 8 + g) * HPAD + tq;
#pragma unroll
        for (int ks = 0; ks < 8; ks++) {
            unsigned int b0 = wh[brow + ks * 8];
            unsigned int b1 = wh[brow + ks * 8 + 4];
            asm volatile(
                "mma.sync.aligned.m16n8k16.row.col.f32.f16.f16.f32 "
                "{%0,%1,%2,%3}, {%4,%5,%6,%7}, {%8,%9}, {%0,%1,%2,%3};"
                : "+f"(acc[nt][0]), "+f"(acc[nt][1]), "+f"(acc[nt][2]), "+f"(acc[nt][3])
                : "r"(A[ks][0]), "r"(A[ks][1]), "r"(A[ks][2]), "r"(A[ks][3]),
                  "r"(b0), "r"(b1));
        }
    }

    int gn0 = node0 + nodeW + g;
    int gn1 = gn0 + 8;
    unsigned int* s1u = (unsigned int*)g_s1h;
#pragma unroll
    for (int nt = 0; nt < 8; nt++) {
        int ch = (nt * 8 + tq * 2) >> 1;
        if (gn0 < N) s1u[(size_t)gn0 * 32 + ch] = pack_h2(acc[nt][0], acc[nt][1]);
        if (gn1 < N) s1u[(size_t)gn1 * 32 + ch] = pack_h2(acc[nt][2], acc[nt][3]);
    }
}

// ---------------- scale1: s1h *= dinv ----------------
__global__ void k_scale1(int N) {
    int tid = blockIdx.x * blockDim.x + threadIdx.x;
    int node = tid >> 2, q = tid & 3;
    if (node >= N) return;
    float d = g_dinv[node];
    uint4* p = (uint4*)g_s1h + (size_t)node * 8 + q * 2;
#pragma unroll
    for (int u = 0; u < 2; u++) {
        uint4 v = p[u];
        unsigned int* vi = (unsigned int*)&v;
#pragma unroll
        for (int j = 0; j < 4; j++) {
            float2 f = __half22float2(*(__half2*)&vi[j]);
            vi[j] = pack_h2(d * f.x, d * f.y);
        }
        p[u] = v;
    }
}

// ---- agg1: 8 lanes x uint4 per 128B row; 16 edges/iter; pipelined index loads ----
__global__ __launch_bounds__(256) void k_agg1(const float* __restrict__ b1, int N) {
    int w = (blockIdx.x * blockDim.x + threadIdx.x) >> 5;
    int lane = threadIdx.x & 31;
    if (w >= N) return;
    int h = lane & 7, sub = lane >> 3;
    int beg = g_ptr[w], end = g_ptr[w + 1];
    const uint4* s1 = (const uint4*)g_s1h;

    float a0 = 0.f, a1 = 0.f, a2 = 0.f, a3 = 0.f;
    float a4 = 0.f, a5 = 0.f, a6 = 0.f, a7 = 0.f;
    int nE = end - beg;
    int nChunk = nE >> 4;
    if (nChunk > 0) {
        int base = beg + sub;
        int r0 = g_rows[base],     r1 = g_rows[base + 4];
        int r2 = g_rows[base + 8], r3 = g_rows[base + 12];
        for (int c = 0; c < nChunk; c++) {
            uint4 u0 = s1[(size_t)r0 * 8 + h];
            uint4 u1 = s1[(size_t)r1 * 8 + h];
            uint4 u2 = s1[(size_t)r2 * 8 + h];
            uint4 u3 = s1[(size_t)r3 * 8 + h];
            if (c + 1 < nChunk) {              // prefetch next chunk's indices
                int nb = beg + (c + 1) * 16 + sub;
                r0 = g_rows[nb];      r1 = g_rows[nb + 4];
                r2 = g_rows[nb + 8];  r3 = g_rows[nb + 12];
            }
            float2 f;
            f = __half22float2(*(__half2*)&u0.x); a0 += f.x; a1 += f.y;
            f = __half22float2(*(__half2*)&u0.y); a2 += f.x; a3 += f.y;
            f = __half22float2(*(__half2*)&u0.z); a4 += f.x; a5 += f.y;
            f = __half22float2(*(__half2*)&u0.w); a6 += f.x; a7 += f.y;
            f = __half22float2(*(__half2*)&u1.x); a0 += f.x; a1 += f.y;
            f = __half22float2(*(__half2*)&u1.y); a2 += f.x; a3 += f.y;
            f = __half22float2(*(__half2*)&u1.z); a4 += f.x; a5 += f.y;
            f = __half22float2(*(__half2*)&u1.w); a6 += f.x; a7 += f.y;
            f = __half22float2(*(__half2*)&u2.x); a0 += f.x; a1 += f.y;
            f = __half22float2(*(__half2*)&u2.y); a2 += f.x; a3 += f.y;
            f = __half22float2(*(__half2*)&u2.z); a4 += f.x; a5 += f.y;
            f = __half22float2(*(__half2*)&u2.w); a6 += f.x; a7 += f.y;
            f = __half22float2(*(__half2*)&u3.x); a0 += f.x; a1 += f.y;
            f = __half22float2(*(__half2*)&u3.y); a2 += f.x; a3 += f.y;
            f = __half22float2(*(__half2*)&u3.z); a4 += f.x; a5 += f.y;
            f = __half22float2(*(__half2*)&u3.w); a6 += f.x; a7 += f.y;
        }
    }
    for (int i = beg + nChunk * 16 + sub; i < end; i += 4) {
        uint4 u = s1[(size_t)g_rows[i] * 8 + h];
        float2 f;
        f = __half22float2(*(__half2*)&u.x); a0 += f.x; a1 += f.y;
        f = __half22float2(*(__half2*)&u.y); a2 += f.x; a3 += f.y;
        f = __half22float2(*(__half2*)&u.z); a4 += f.x; a5 += f.y;
        f = __half22float2(*(__half2*)&u.w); a6 += f.x; a7 += f.y;
    }
#pragma unroll
    for (int o = 8; o <= 16; o <<= 1) {
        a0 += __shfl_xor_sync(0xffffffffu, a0, o);
        a1 += __shfl_xor_sync(0xffffffffu, a1, o);
        a2 += __shfl_xor_sync(0xffffffffu, a2, o);
        a3 += __shfl_xor_sync(0xffffffffu, a3, o);
        a4 += __shfl_xor_sync(0xffffffffu, a4, o);
        a5 += __shfl_xor_sync(0xffffffffu, a5, o);
        a6 += __shfl_xor_sync(0xffffffffu, a6, o);
        a7 += __shfl_xor_sync(0xffffffffu, a7, o);
    }
    if (sub == 0) {
        uint4 us = s1[(size_t)w * 8 + h];
        float2 f;
        f = __half22float2(*(__half2*)&us.x); a0 += f.x; a1 += f.y;
        f = __half22float2(*(__half2*)&us.y); a2 += f.x; a3 += f.y;
        f = __half22float2(*(__half2*)&us.z); a4 += f.x; a5 += f.y;
        f = __half22float2(*(__half2*)&us.w); a6 += f.x; a7 += f.y;
        float d = g_dinv[w];
        float4 b0 = ((const float4*)b1)[h * 2];
        float4 b2v = ((const float4*)b1)[h * 2 + 1];
        uint4 zz;
        zz.x = pack_h2(fmaxf(fmaf(d, a0, b0.x), 0.f),  fmaxf(fmaf(d, a1, b0.y), 0.f));
        zz.y = pack_h2(fmaxf(fmaf(d, a2, b0.z), 0.f),  fmaxf(fmaf(d, a3, b0.w), 0.f));
        zz.z = pack_h2(fmaxf(fmaf(d, a4, b2v.x), 0.f), fmaxf(fmaf(d, a5, b2v.y), 0.f));
        zz.w = pack_h2(fmaxf(fmaf(d, a6, b2v.z), 0.f), fmaxf(fmaf(d, a7, b2v.w), 0.f));
        ((uint4*)g_z1h)[(size_t)w * 8 + h] = zz;
    }
}

// ------ GEMM2: s2h = fp16( dinv * (z1h @ W2) )   [N,64]x[64,32], z1 in fp16 ------
__global__ __launch_bounds__(256) void k_gemm2(const float* __restrict__ W2, int N) {
    __shared__ float Ws[HDIM * ODIM];
    __shared__ float zs[HDIM * XSTR];
    int t = threadIdx.x;
    for (int i = t; i < HDIM * ODIM; i += 256) Ws[i] = W2[i];

    int node0 = blockIdx.x * 64;
    int lane = t & 31, wrp = t >> 5;
    const unsigned int* z1u = (const unsigned int*)g_z1h;
#pragma unroll
    for (int rep = 0; rep < 8; rep++) {
        int n = wrp * 8 + rep;
        int gn = node0 + n;
        unsigned int u = (gn < N) ? z1u[(size_t)gn * 32 + lane] : 0u;
        float2 f = __half22float2(*(__half2*)&u);
        zs[(2 * lane) * XSTR + n]     = f.x;
        zs[(2 * lane + 1) * XSTR + n] = f.y;
    }
    __syncthreads();

    int n = t & 63;
    int og = t >> 6;
    float acc[8];
#pragma unroll
    for (int i = 0; i < 8; i++) acc[i] = 0.f;
    const float4* Ws4 = (const float4*)Ws;
#pragma unroll 4
    for (int k = 0; k < HDIM; k++) {
        float xv = zs[k * XSTR + n];
        float4 w0 = Ws4[k * 8 + og * 2];
        float4 w1 = Ws4[k * 8 + og * 2 + 1];
        acc[0] = fmaf(xv, w0.x, acc[0]); acc[1] = fmaf(xv, w0.y, acc[1]);
        acc[2] = fmaf(xv, w0.z, acc[2]); acc[3] = fmaf(xv, w0.w, acc[3]);
        acc[4] = fmaf(xv, w1.x, acc[4]); acc[5] = fmaf(xv, w1.y, acc[5]);
        acc[6] = fmaf(xv, w1.z, acc[6]); acc[7] = fmaf(xv, w1.w, acc[7]);
    }
    int gn = node0 + n;
    if (gn < N) {
        float d = g_dinv[gn];
        unsigned int p[4];
#pragma unroll
        for (int j = 0; j < 4; j++) p[j] = pack_h2(d * acc[2 * j], d * acc[2 * j + 1]);
        *(uint4*)(g_s2h + (size_t)gn * ODIM + og * 8) = make_uint4(p[0], p[1], p[2], p[3]);
    }
}

// ---- agg2: 8 lanes x uint2 per 64B row; 16 edges/iter; pipelined index loads ----
__global__ __launch_bounds__(256) void k_agg2(const float* __restrict__ b2, int N) {
    int w = (blockIdx.x * blockDim.x + threadIdx.x) >> 5;
    int lane = threadIdx.x & 31;
    if (w >= N) return;
    int h = lane & 7, sub = lane >> 3;
    int beg = g_ptr[w], end = g_ptr[w + 1];
    const uint2* s2 = (const uint2*)g_s2h;

    float a0 = 0.f, a1 = 0.f, a2 = 0.f, a3 = 0.f;
    int nE = end - beg;
    int nChunk = nE >> 4;
    if (nChunk > 0) {
        int base = beg + sub;
        int r0 = g_rows[base],     r1 = g_rows[base + 4];
        int r2 = g_rows[base + 8], r3 = g_rows[base + 12];
        for (int c = 0; c < nChunk; c++) {
            uint2 u0 = s2[(size_t)r0 * 8 + h];
            uint2 u1 = s2[(size_t)r1 * 8 + h];
            uint2 u2 = s2[(size_t)r2 * 8 + h];
            uint2 u3 = s2[(size_t)r3 * 8 + h];
            if (c + 1 < nChunk) {
                int nb = beg + (c + 1) * 16 + sub;
                r0 = g_rows[nb];      r1 = g_rows[nb + 4];
                r2 = g_rows[nb + 8];  r3 = g_rows[nb + 12];
            }
            float2 f;
            f = __half22float2(*(__half2*)&u0.x); a0 += f.x; a1 += f.y;
            f = __half22float2(*(__half2*)&u0.y); a2 += f.x; a3 += f.y;
            f = __half22float2(*(__half2*)&u1.x); a0 += f.x; a1 += f.y;
            f = __half22float2(*(__half2*)&u1.y); a2 += f.x; a3 += f.y;
            f = __half22float2(*(__half2*)&u2.x); a0 += f.x; a1 += f.y;
            f = __half22float2(*(__half2*)&u2.y); a2 += f.x; a3 += f.y;
            f = __half22float2(*(__half2*)&u3.x); a0 += f.x; a1 += f.y;
            f = __half22float2(*(__half2*)&u3.y); a2 += f.x; a3 += f.y;
        }
    }
    for (int i = beg + nChunk * 16 + sub; i < end; i += 4) {
        uint2 u = s2[(size_t)g_rows[i] * 8 + h];
        float2 f;
        f = __half22float2(*(__half2*)&u.x); a0 += f.x; a1 += f.y;
        f = __half22float2(*(__half2*)&u.y); a2 += f.x; a3 += f.y;
    }
#pragma unroll
    for (int o = 8; o <= 16; o <<= 1) {
        a0 += __shfl_xor_sync(0xffffffffu, a0, o);
        a1 += __shfl_xor_sync(0xffffffffu, a1, o);
        a2 += __shfl_xor_sync(0xffffffffu, a2, o);
        a3 += __shfl_xor_sync(0xffffffffu, a3, o);
    }
    if (sub == 0) {
        uint2 us = s2[(size_t)w * 8 + h];
        float2 f;
        f = __half22float2(*(__half2*)&us.x); a0 += f.x; a1 += f.y;
        f = __half22float2(*(__half2*)&us.y); a2 += f.x; a3 += f.y;
        float d = g_dinv[w];
        float4 bb = ((const float4*)b2)[h];
        float4 z;
        z.x = fmaf(d, a0, bb.x);
        z.y = fmaf(d, a1, bb.y);
        z.z = fmaf(d, a2, bb.z);
        z.w = fmaf(d, a3, bb.w);
        ((float4*)g_z2)[(size_t)w * 8 + h] = z;
    }
}

// ---------------- decode: out[p] = dot(z2[a], z2[b]) over 32 dims ----------------
__global__ __launch_bounds__(256) void k_decode(const void* __restrict__ eli,
                                                float* __restrict__ out, int EL) {
    int t = blockIdx.x * blockDim.x + threadIdx.x;
    int p = t >> 3;
    int j = t & 7;
    if (p >= EL) return;
    int is32 = g_is32;
    int a = edge_at(eli, p, is32);
    int b = edge_at(eli, (long long)EL + p, is32);
    float4 va = ((const float4*)g_z2)[a * 8 + j];
    float4 vb = ((const float4*)g_z2)[b * 8 + j];
    float s = va.x * vb.x + va.y * vb.y + va.z * vb.z + va.w * vb.w;
    s += __shfl_down_sync(0xffffffffu, s, 4, 8);
    s += __shfl_down_sync(0xffffffffu, s, 2, 8);
    s += __shfl_down_sync(0xffffffffu, s, 1, 8);
    if (j == 0) out[p] = s;
}

// ---------------- launch ----------------
extern "C" void kernel_launch(void* const* d_in, const int* in_sizes, int n_in,
                              void* d_out, int out_size) {
    const float* x   = (const float*)d_in[0];
    const float* W1  = (const float*)d_in[1];
    const float* b1  = (const float*)d_in[2];
    const float* W2  = (const float*)d_in[3];
    const float* b2  = (const float*)d_in[4];
    const void*  ei  = d_in[5];
    const void*  eli = d_in[6];

    int H  = in_sizes[2];                 // 64
    int F  = in_sizes[1] / H;             // 128
    int N  = in_sizes[0] / F;             // 100000
    int E  = in_sizes[5] / 2;             // 3200000
    int EL = in_sizes[6] / 2;             // 200000
    float* out = (float*)d_out;

    int NB1024 = (N + 1023) / 1024;
    int EQ = (E + 3) / 4;
    int gemm1_smem = (128 * HPAD + 64 * HPAD) * sizeof(unsigned int);
    cudaFuncSetAttribute(k_gemm1, cudaFuncAttributeMaxDynamicSharedMemorySize, gemm1_smem);

    cudaStream_t s2;
    cudaStreamCreateWithFlags(&s2, cudaStreamNonBlocking);
    cudaEvent_t ev_fork, ev_scan, ev_sc1;
    cudaEventCreateWithFlags(&ev_fork, cudaEventDisableTiming);
    cudaEventCreateWithFlags(&ev_scan, cudaEventDisableTiming);
    cudaEventCreateWithFlags(&ev_sc1, cudaEventDisableTiming);

    // fork: raw gemm1 depends on nothing
    cudaEventRecord(ev_fork, 0);
    cudaStreamWaitEvent(s2, ev_fork, 0);
    k_gemm1<<<(N + 127) / 128, 256, gemm1_smem, s2>>>(x, W1, N);

    // CSR build on main stream
    k_prep<<<(N + 255) / 256, 256>>>(ei, E, N);
    k_count<<<(EQ + 255) / 256, 256>>>(ei, E);
    k_scan<<<NB1024, 1024>>>(N, E);
    cudaEventRecord(ev_scan, 0);

    // side stream: scale1 after scan (overlaps with scatter on main stream)
    cudaStreamWaitEvent(s2, ev_scan, 0);
    k_scale1<<<(N * 4 + 255) / 256, 256, 0, s2>>>(N);
    cudaEventRecord(ev_sc1, s2);

    k_scatter<<<(EQ + 255) / 256, 256>>>(ei, E);
    cudaStreamWaitEvent(0, ev_sc1, 0);

    // serial tail
    k_agg1<<<(N + 7) / 8, 256>>>(b1, N);
    k_gemm2<<<(N + 63) / 64, 256>>>(W2, N);
    k_agg2<<<(N + 7) / 8, 256>>>(b2, N);
    k_decode<<<(EL * 8 + 255) / 256, 256>>>(eli, out, EL);

    cudaEventDestroy(ev_fork);
    cudaEventDestroy(ev_scan);
    cudaEventDestroy(ev_sc1);
    cudaStreamDestroy(s2);
}

// round 14
// speedup vs baseline: 1.0510x; 1.0510x over previous
#include <cuda_runtime.h>
#include <cuda_fp16.h>

// ---------------- fixed problem capacities (dataset is fixed) ----------------
#define NMAX 100000
#define EMAX 3200000
#define HDIM 64
#define ODIM 32
#define FDIM 128
#define XSTR 65    // padded fp32 [k][n] stride (gemm2)
#define HPAD 68    // padded half2/uint stride (=136 halves) for tensor gemm smem

// ---------------- device scratch (no allocations allowed) ----------------
__device__ int   g_is32;                              // 1 if edge indices are int32
__device__ int   g_ecnt[NMAX];                        // in-degree (no self loop)
__device__ int   g_ptr[NMAX + 1];                     // CSR offsets
__device__ unsigned long long g_scanstate[128];       // lookback: (flag<<32)|sum
__device__ float g_dinv[NMAX];                        // 1/sqrt(deg+1)
__device__ __align__(16) int     g_rank[EMAX];        // per-edge rank within dst
__device__ __align__(16) int     g_rows[EMAX];        // CSR adjacency: src per slot
__device__ __align__(16) __half2 g_s1h[NMAX * 32];    // fp16 dinv*(x@W1): 64 vals/node
__device__ __align__(16) __half2 g_z1h[NMAX * 32];    // fp16 relu layer-1 output
__device__ __align__(16) __half  g_s2h[NMAX * ODIM];  // fp16 dinv*(z1@W2): 32 vals/node
__device__ __align__(16) float   g_z2[NMAX * ODIM];   // layer-2 output (fp32)

__device__ __forceinline__ int edge_at(const void* p, long long j, int is32) {
    if (is32) return ((const int*)p)[j];
    return (int)((const long long*)p)[j];
}
__device__ __forceinline__ unsigned int pack_h2(float a, float b) {
    __half2 h = __floats2half2_rn(a, b);
    return *reinterpret_cast<unsigned int*>(&h);
}

// ---------------- prep: dtype detect + zero counters/flags ----------------
__global__ void k_prep(const void* ei, int E, int N) {
    int i = blockIdx.x * blockDim.x + threadIdx.x;
    if (i < N) g_ecnt[i] = 0;
    if (i < 128) g_scanstate[i] = 0ull;
    if (blockIdx.x == 0) {
        __shared__ int bad;
        if (threadIdx.x == 0) bad = 0;
        __syncthreads();
        int n = (2 * E < 256) ? 2 * E : 256;
        if (threadIdx.x < n) {
            long long v = ((const long long*)ei)[threadIdx.x];
            if (v < 0 || v >= NMAX) atomicOr(&bad, 1);
        }
        __syncthreads();
        if (threadIdx.x == 0) g_is32 = bad;
    }
}

// ------- count: 4 edges/thread; also records per-edge rank within its dst -------
__global__ void k_count(const void* __restrict__ ei, int E) {
    int q = blockIdx.x * blockDim.x + threadIdx.x;
    int e0 = q * 4;
    if (e0 >= E) return;
    int is32 = g_is32;
    if (e0 + 4 <= E) {
        int4 c;
        if (is32) {
            c = *(const int4*)((const int*)ei + E + e0);
        } else {
            const longlong2* p = (const longlong2*)((const long long*)ei + E + e0);
            longlong2 a = p[0], b = p[1];
            c = make_int4((int)a.x, (int)a.y, (int)b.x, (int)b.y);
        }
        int4 rk;
        rk.x = atomicAdd(&g_ecnt[c.x], 1);
        rk.y = atomicAdd(&g_ecnt[c.y], 1);
        rk.z = atomicAdd(&g_ecnt[c.z], 1);
        rk.w = atomicAdd(&g_ecnt[c.w], 1);
        *(int4*)(g_rank + e0) = rk;
    } else {
        for (int e = e0; e < E; e++) {
            int cc = edge_at(ei, (long long)E + e, is32);
            g_rank[e] = atomicAdd(&g_ecnt[cc], 1);
        }
    }
}

// ---- single-pass exclusive scan: warp scan + warp-parallel decoupled lookback ----
__global__ void k_scan(int N, int E) {
    __shared__ int wsum[32];
    __shared__ int s_prefix;
    int t = threadIdx.x, b = blockIdx.x;
    int lane = t & 31, wid = t >> 5;
    int i = b * 1024 + t;
    int v = (i < N) ? g_ecnt[i] : 0;

    int s = v;
#pragma unroll
    for (int o = 1; o < 32; o <<= 1) {
        int y = __shfl_up_sync(0xffffffffu, s, o);
        if (lane >= o) s += y;
    }
    if (lane == 31) wsum[wid] = s;
    __syncthreads();
    if (wid == 0) {
        int ws = wsum[lane];
#pragma unroll
        for (int o = 1; o < 32; o <<= 1) {
            int y = __shfl_up_sync(0xffffffffu, ws, o);
            if (lane >= o) ws += y;
        }
        wsum[lane] = ws;
    }
    __syncthreads();
    int incl = s + (wid ? wsum[wid - 1] : 0);
    int btotal = wsum[31];

    if (wid == 0) {
        if (b == 0) {
            if (lane == 0) {
                atomicExch(&g_scanstate[0], (2ull << 32) | (unsigned int)btotal);
                s_prefix = 0;
            }
        } else {
            if (lane == 0)
                atomicExch(&g_scanstate[b], (1ull << 32) | (unsigned int)btotal);
            __syncwarp();
            long long pref = 0;
            int base = b;
            while (true) {
                int idx = base - 32 + lane;
                bool valid = idx >= 0;
                unsigned long long st = 0;
                if (valid) {
                    do { st = atomicAdd(&g_scanstate[idx], 0ull); } while ((st >> 32) == 0);
                }
                unsigned m = __ballot_sync(0xffffffffu, valid && (st >> 32) == 2ull);
                int cut = m ? (31 - __clz(m)) : 32;
                bool contrib = valid && (cut == 32 || lane >= cut);
                long long c = contrib ? (long long)(st & 0xffffffffull) : 0;
#pragma unroll
                for (int o = 16; o; o >>= 1) c += __shfl_xor_sync(0xffffffffu, c, o);
                pref += c;
                if (cut != 32) break;
                base -= 32;
            }
            if (lane == 0) {
                atomicExch(&g_scanstate[b],
                           (2ull << 32) | (unsigned int)(pref + (long long)btotal));
                s_prefix = (int)pref;
            }
        }
    }
    __syncthreads();
    int p = s_prefix + incl - v;
    if (i < N) {
        g_ptr[i] = p;
        g_dinv[i] = rsqrtf((float)(g_ecnt[i] + 1));
    }
    if (i == 0) g_ptr[N] = E;
}

// ------- scatter (atomic-free fill): g_rows[ptr[c]+rank] = r -------
__global__ void k_scatter(const void* __restrict__ ei, int E) {
    int q = blockIdx.x * blockDim.x + threadIdx.x;
    int e0 = q * 4;
    if (e0 >= E) return;
    int is32 = g_is32;
    if (e0 + 4 <= E) {
        int4 r, c;
        if (is32) {
            r = *(const int4*)((const int*)ei + e0);
            c = *(const int4*)((const int*)ei + E + e0);
        } else {
            const longlong2* rp = (const longlong2*)((const long long*)ei + e0);
            const longlong2* cp = (const longlong2*)((const long long*)ei + E + e0);
            longlong2 ra = rp[0], rb = rp[1], ca = cp[0], cb = cp[1];
            r = make_int4((int)ra.x, (int)ra.y, (int)rb.x, (int)rb.y);
            c = make_int4((int)ca.x, (int)ca.y, (int)cb.x, (int)cb.y);
        }
        int4 rk = *(const int4*)(g_rank + e0);
        g_rows[g_ptr[c.x] + rk.x] = r.x;
        g_rows[g_ptr[c.y] + rk.y] = r.y;
        g_rows[g_ptr[c.z] + rk.z] = r.z;
        g_rows[g_ptr[c.w] + rk.w] = r.w;
    } else {
        for (int e = e0; e < E; e++) {
            int rr = edge_at(ei, e, is32);
            int cc = edge_at(ei, (long long)E + e, is32);
            g_rows[g_ptr[cc] + g_rank[e]] = rr;
        }
    }
}

// ---------------- GEMM1 (tensor cores): s1h_raw = fp16( x @ W1 ) ----------------
__global__ __launch_bounds__(256) void k_gemm1(const float* __restrict__ x,
                                               const float* __restrict__ W1, int N) {
    extern __shared__ unsigned int smu[];
    unsigned int* xh = smu;
    unsigned int* wh = smu + 128 * HPAD;
    __half* whh = (__half*)wh;
    int t = threadIdx.x;

    for (int i = t; i < FDIM * HDIM; i += 256) {
        int k = i >> 6, n = i & 63;
        whh[n * (2 * HPAD) + k] = __float2half_rn(W1[i]);
    }
    int node0 = blockIdx.x * 128;
    const float4* x4 = (const float4*)x;
    for (int i = t; i < 128 * 32; i += 256) {
        int nd = i >> 5, kq = i & 31;
        int gn = node0 + nd;
        float4 v = (gn < N) ? x4[(size_t)gn * 32 + kq] : make_float4(0.f, 0.f, 0.f, 0.f);
        xh[nd * HPAD + kq * 2]     = pack_h2(v.x, v.y);
        xh[nd * HPAD + kq * 2 + 1] = pack_h2(v.z, v.w);
    }
    __syncthreads();

    int wid = t >> 5, lane = t & 31;
    int g = lane >> 2, tq = lane & 3;
    int nodeW = wid * 16;

    unsigned int A[8][4];
#pragma unroll
    for (int ks = 0; ks < 8; ks++) {
        int base0 = (nodeW + g) * HPAD + ks * 8 + tq;
        int base1 = (nodeW + g + 8) * HPAD + ks * 8 + tq;
        A[ks][0] = xh[base0];
        A[ks][1] = xh[base1];
        A[ks][2] = xh[base0 + 4];
        A[ks][3] = xh[base1 + 4];
    }

    float acc[8][4];
#pragma unroll
    for (int nt = 0; nt < 8; nt++)
#pragma unroll
        for (int j = 0; j < 4; j++) acc[nt][j] = 0.f;

#pragma unroll
    for (int nt = 0; nt < 8; nt++) {
        int brow = (nt * 8 + g) * HPAD + tq;
#pragma unroll
        for (int ks = 0; ks < 8; ks++) {
            unsigned int b0 = wh[brow + ks * 8];
            unsigned int b1 = wh[brow + ks * 8 + 4];
            asm volatile(
                "mma.sync.aligned.m16n8k16.row.col.f32.f16.f16.f32 "
                "{%0,%1,%2,%3}, {%4,%5,%6,%7}, {%8,%9}, {%0,%1,%2,%3};"
                : "+f"(acc[nt][0]), "+f"(acc[nt][1]), "+f"(acc[nt][2]), "+f"(acc[nt][3])
                : "r"(A[ks][0]), "r"(A[ks][1]), "r"(A[ks][2]), "r"(A[ks][3]),
                  "r"(b0), "r"(b1));
        }
    }

    int gn0 = node0 + nodeW + g;
    int gn1 = gn0 + 8;
    unsigned int* s1u = (unsigned int*)g_s1h;
#pragma unroll
    for (int nt = 0; nt < 8; nt++) {
        int ch = (nt * 8 + tq * 2) >> 1;
        if (gn0 < N) s1u[(size_t)gn0 * 32 + ch] = pack_h2(acc[nt][0], acc[nt][1]);
        if (gn1 < N) s1u[(size_t)gn1 * 32 + ch] = pack_h2(acc[nt][2], acc[nt][3]);
    }
}

// ---------------- scale1: s1h *= dinv ----------------
__global__ void k_scale1(int N) {
    int tid = blockIdx.x * blockDim.x + threadIdx.x;
    int node = tid >> 2, q = tid & 3;
    if (node >= N) return;
    float d = g_dinv[node];
    uint4* p = (uint4*)g_s1h + (size_t)node * 8 + q * 2;
#pragma unroll
    for (int u = 0; u < 2; u++) {
        uint4 v = p[u];
        unsigned int* vi = (unsigned int*)&v;
#pragma unroll
        for (int j = 0; j < 4; j++) {
            float2 f = __half22float2(*(__half2*)&vi[j]);
            vi[j] = pack_h2(d * f.x, d * f.y);
        }
        p[u] = v;
    }
}

// ---- agg1: 8 lanes x uint4(16B) per 128B row; 4 edge-parities, 16 edges/iter ----
// z1 stored fp16 (uint4 per lane) -> half the epilogue traffic.
__global__ __launch_bounds__(256) void k_agg1(const float* __restrict__ b1, int N) {
    int w = (blockIdx.x * blockDim.x + threadIdx.x) >> 5;
    int lane = threadIdx.x & 31;
    if (w >= N) return;
    int h = lane & 7, sub = lane >> 3;
    int beg = g_ptr[w], end = g_ptr[w + 1];
    const uint4* s1 = (const uint4*)g_s1h;

    float a0 = 0.f, a1 = 0.f, a2 = 0.f, a3 = 0.f;
    float a4 = 0.f, a5 = 0.f, a6 = 0.f, a7 = 0.f;
    int nE = end - beg;
    int nChunk = nE >> 4;
    for (int c = 0; c < nChunk; c++) {
        int base = beg + c * 16 + sub;
        int r0 = g_rows[base],     r1 = g_rows[base + 4];
        int r2 = g_rows[base + 8], r3 = g_rows[base + 12];
        uint4 u0 = s1[(size_t)r0 * 8 + h];
        uint4 u1 = s1[(size_t)r1 * 8 + h];
        uint4 u2 = s1[(size_t)r2 * 8 + h];
        uint4 u3 = s1[(size_t)r3 * 8 + h];
        float2 f;
        f = __half22float2(*(__half2*)&u0.x); a0 += f.x; a1 += f.y;
        f = __half22float2(*(__half2*)&u0.y); a2 += f.x; a3 += f.y;
        f = __half22float2(*(__half2*)&u0.z); a4 += f.x; a5 += f.y;
        f = __half22float2(*(__half2*)&u0.w); a6 += f.x; a7 += f.y;
        f = __half22float2(*(__half2*)&u1.x); a0 += f.x; a1 += f.y;
        f = __half22float2(*(__half2*)&u1.y); a2 += f.x; a3 += f.y;
        f = __half22float2(*(__half2*)&u1.z); a4 += f.x; a5 += f.y;
        f = __half22float2(*(__half2*)&u1.w); a6 += f.x; a7 += f.y;
        f = __half22float2(*(__half2*)&u2.x); a0 += f.x; a1 += f.y;
        f = __half22float2(*(__half2*)&u2.y); a2 += f.x; a3 += f.y;
        f = __half22float2(*(__half2*)&u2.z); a4 += f.x; a5 += f.y;
        f = __half22float2(*(__half2*)&u2.w); a6 += f.x; a7 += f.y;
        f = __half22float2(*(__half2*)&u3.x); a0 += f.x; a1 += f.y;
        f = __half22float2(*(__half2*)&u3.y); a2 += f.x; a3 += f.y;
        f = __half22float2(*(__half2*)&u3.z); a4 += f.x; a5 += f.y;
        f = __half22float2(*(__half2*)&u3.w); a6 += f.x; a7 += f.y;
    }
    for (int i = beg + nChunk * 16 + sub; i < end; i += 4) {
        uint4 u = s1[(size_t)g_rows[i] * 8 + h];
        float2 f;
        f = __half22float2(*(__half2*)&u.x); a0 += f.x; a1 += f.y;
        f = __half22float2(*(__half2*)&u.y); a2 += f.x; a3 += f.y;
        f = __half22float2(*(__half2*)&u.z); a4 += f.x; a5 += f.y;
        f = __half22float2(*(__half2*)&u.w); a6 += f.x; a7 += f.y;
    }
#pragma unroll
    for (int o = 8; o <= 16; o <<= 1) {
        a0 += __shfl_xor_sync(0xffffffffu, a0, o);
        a1 += __shfl_xor_sync(0xffffffffu, a1, o);
        a2 += __shfl_xor_sync(0xffffffffu, a2, o);
        a3 += __shfl_xor_sync(0xffffffffu, a3, o);
        a4 += __shfl_xor_sync(0xffffffffu, a4, o);
        a5 += __shfl_xor_sync(0xffffffffu, a5, o);
        a6 += __shfl_xor_sync(0xffffffffu, a6, o);
        a7 += __shfl_xor_sync(0xffffffffu, a7, o);
    }
    if (sub == 0) {
        uint4 us = s1[(size_t)w * 8 + h];
        float2 f;
        f = __half22float2(*(__half2*)&us.x); a0 += f.x; a1 += f.y;
        f = __half22float2(*(__half2*)&us.y); a2 += f.x; a3 += f.y;
        f = __half22float2(*(__half2*)&us.z); a4 += f.x; a5 += f.y;
        f = __half22float2(*(__half2*)&us.w); a6 += f.x; a7 += f.y;
        float d = g_dinv[w];
        float4 b0 = ((const float4*)b1)[h * 2];
        float4 b2v = ((const float4*)b1)[h * 2 + 1];
        uint4 zz;
        zz.x = pack_h2(fmaxf(fmaf(d, a0, b0.x), 0.f),  fmaxf(fmaf(d, a1, b0.y), 0.f));
        zz.y = pack_h2(fmaxf(fmaf(d, a2, b0.z), 0.f),  fmaxf(fmaf(d, a3, b0.w), 0.f));
        zz.z = pack_h2(fmaxf(fmaf(d, a4, b2v.x), 0.f), fmaxf(fmaf(d, a5, b2v.y), 0.f));
        zz.w = pack_h2(fmaxf(fmaf(d, a6, b2v.z), 0.f), fmaxf(fmaf(d, a7, b2v.w), 0.f));
        ((uint4*)g_z1h)[(size_t)w * 8 + h] = zz;
    }
}

// ------ GEMM2: s2h = fp16( dinv * (z1h @ W2) )   [N,64]x[64,32], z1 in fp16 ------
__global__ __launch_bounds__(256) void k_gemm2(const float* __restrict__ W2, int N) {
    __shared__ float Ws[HDIM * ODIM];
    __shared__ float zs[HDIM * XSTR];
    int t = threadIdx.x;
    for (int i = t; i < HDIM * ODIM; i += 256) Ws[i] = W2[i];

    int node0 = blockIdx.x * 64;
    int lane = t & 31, wrp = t >> 5;
    const unsigned int* z1u = (const unsigned int*)g_z1h;   // 32 uints per node
#pragma unroll
    for (int rep = 0; rep < 8; rep++) {
        int n = wrp * 8 + rep;
        int gn = node0 + n;
        unsigned int u = (gn < N) ? z1u[(size_t)gn * 32 + lane] : 0u;
        float2 f = __half22float2(*(__half2*)&u);
        zs[(2 * lane) * XSTR + n]     = f.x;
        zs[(2 * lane + 1) * XSTR + n] = f.y;
    }
    __syncthreads();

    int n = t & 63;
    int og = t >> 6;
    float acc[8];
#pragma unroll
    for (int i = 0; i < 8; i++) acc[i] = 0.f;
    const float4* Ws4 = (const float4*)Ws;
#pragma unroll 4
    for (int k = 0; k < HDIM; k++) {
        float xv = zs[k * XSTR + n];
        float4 w0 = Ws4[k * 8 + og * 2];
        float4 w1 = Ws4[k * 8 + og * 2 + 1];
        acc[0] = fmaf(xv, w0.x, acc[0]); acc[1] = fmaf(xv, w0.y, acc[1]);
        acc[2] = fmaf(xv, w0.z, acc[2]); acc[3] = fmaf(xv, w0.w, acc[3]);
        acc[4] = fmaf(xv, w1.x, acc[4]); acc[5] = fmaf(xv, w1.y, acc[5]);
        acc[6] = fmaf(xv, w1.z, acc[6]); acc[7] = fmaf(xv, w1.w, acc[7]);
    }
    int gn = node0 + n;
    if (gn < N) {
        float d = g_dinv[gn];
        unsigned int p[4];
#pragma unroll
        for (int j = 0; j < 4; j++) p[j] = pack_h2(d * acc[2 * j], d * acc[2 * j + 1]);
        *(uint4*)(g_s2h + (size_t)gn * ODIM + og * 8) = make_uint4(p[0], p[1], p[2], p[3]);
    }
}

// ---- agg2: 8 lanes x uint2(8B) per 64B row; 4 edge-parities, 16 edges/iter ----
__global__ __launch_bounds__(256) void k_agg2(const float* __restrict__ b2, int N) {
    int w = (blockIdx.x * blockDim.x + threadIdx.x) >> 5;
    int lane = threadIdx.x & 31;
    if (w >= N) return;
    int h = lane & 7, sub = lane >> 3;
    int beg = g_ptr[w], end = g_ptr[w + 1];
    const uint2* s2 = (const uint2*)g_s2h;

    float a0 = 0.f, a1 = 0.f, a2 = 0.f, a3 = 0.f;
    int nE = end - beg;
    int nChunk = nE >> 4;
    for (int c = 0; c < nChunk; c++) {
        int base = beg + c * 16 + sub;
        int r0 = g_rows[base],     r1 = g_rows[base + 4];
        int r2 = g_rows[base + 8], r3 = g_rows[base + 12];
        uint2 u0 = s2[(size_t)r0 * 8 + h];
        uint2 u1 = s2[(size_t)r1 * 8 + h];
        uint2 u2 = s2[(size_t)r2 * 8 + h];
        uint2 u3 = s2[(size_t)r3 * 8 + h];
        float2 f;
        f = __half22float2(*(__half2*)&u0.x); a0 += f.x; a1 += f.y;
        f = __half22float2(*(__half2*)&u0.y); a2 += f.x; a3 += f.y;
        f = __half22float2(*(__half2*)&u1.x); a0 += f.x; a1 += f.y;
        f = __half22float2(*(__half2*)&u1.y); a2 += f.x; a3 += f.y;
        f = __half22float2(*(__half2*)&u2.x); a0 += f.x; a1 += f.y;
        f = __half22float2(*(__half2*)&u2.y); a2 += f.x; a3 += f.y;
        f = __half22float2(*(__half2*)&u3.x); a0 += f.x; a1 += f.y;
        f = __half22float2(*(__half2*)&u3.y); a2 += f.x; a3 += f.y;
    }
    for (int i = beg + nChunk * 16 + sub; i < end; i += 4) {
        uint2 u = s2[(size_t)g_rows[i] * 8 + h];
        float2 f;
        f = __half22float2(*(__half2*)&u.x); a0 += f.x; a1 += f.y;
        f = __half22float2(*(__half2*)&u.y); a2 += f.x; a3 += f.y;
    }
#pragma unroll
    for (int o = 8; o <= 16; o <<= 1) {
        a0 += __shfl_xor_sync(0xffffffffu, a0, o);
        a1 += __shfl_xor_sync(0xffffffffu, a1, o);
        a2 += __shfl_xor_sync(0xffffffffu, a2, o);
        a3 += __shfl_xor_sync(0xffffffffu, a3, o);
    }
    if (sub == 0) {
        uint2 us = s2[(size_t)w * 8 + h];
        float2 f;
        f = __half22float2(*(__half2*)&us.x); a0 += f.x; a1 += f.y;
        f = __half22float2(*(__half2*)&us.y); a2 += f.x; a3 += f.y;
        float d = g_dinv[w];
        float4 bb = ((const float4*)b2)[h];
        float4 z;
        z.x = fmaf(d, a0, bb.x);
        z.y = fmaf(d, a1, bb.y);
        z.z = fmaf(d, a2, bb.z);
        z.w = fmaf(d, a3, bb.w);
        ((float4*)g_z2)[(size_t)w * 8 + h] = z;
    }
}

// ---------------- decode: out[p] = dot(z2[a], z2[b]) over 32 dims ----------------
__global__ __launch_bounds__(256) void k_decode(const void* __restrict__ eli,
                                                float* __restrict__ out, int EL) {
    int t = blockIdx.x * blockDim.x + threadIdx.x;
    int p = t >> 3;
    int j = t & 7;
    if (p >= EL) return;
    int is32 = g_is32;
    int a = edge_at(eli, p, is32);
    int b = edge_at(eli, (long long)EL + p, is32);
    float4 va = ((const float4*)g_z2)[a * 8 + j];
    float4 vb = ((const float4*)g_z2)[b * 8 + j];
    float s = va.x * vb.x + va.y * vb.y + va.z * vb.z + va.w * vb.w;
    s += __shfl_down_sync(0xffffffffu, s, 4, 8);
    s += __shfl_down_sync(0xffffffffu, s, 2, 8);
    s += __shfl_down_sync(0xffffffffu, s, 1, 8);
    if (j == 0) out[p] = s;
}

// ---------------- launch ----------------
extern "C" void kernel_launch(void* const* d_in, const int* in_sizes, int n_in,
                              void* d_out, int out_size) {
    const float* x   = (const float*)d_in[0];
    const float* W1  = (const float*)d_in[1];
    const float* b1  = (const float*)d_in[2];
    const float* W2  = (const float*)d_in[3];
    const float* b2  = (const float*)d_in[4];
    const void*  ei  = d_in[5];
    const void*  eli = d_in[6];

    int H  = in_sizes[2];                 // 64
    int F  = in_sizes[1] / H;             // 128
    int N  = in_sizes[0] / F;             // 100000
    int E  = in_sizes[5] / 2;             // 3200000
    int EL = in_sizes[6] / 2;             // 200000
    float* out = (float*)d_out;

    int NB1024 = (N + 1023) / 1024;
    int EQ = (E + 3) / 4;
    int gemm1_smem = (128 * HPAD + 64 * HPAD) * sizeof(unsigned int);
    cudaFuncSetAttribute(k_gemm1, cudaFuncAttributeMaxDynamicSharedMemorySize, gemm1_smem);

    cudaStream_t s2;
    cudaStreamCreateWithFlags(&s2, cudaStreamNonBlocking);
    cudaEvent_t ev_fork, ev_scan, ev_sc1;
    cudaEventCreateWithFlags(&ev_fork, cudaEventDisableTiming);
    cudaEventCreateWithFlags(&ev_scan, cudaEventDisableTiming);
    cudaEventCreateWithFlags(&ev_sc1, cudaEventDisableTiming);

    // fork: raw gemm1 depends on nothing
    cudaEventRecord(ev_fork, 0);
    cudaStreamWaitEvent(s2, ev_fork, 0);
    k_gemm1<<<(N + 127) / 128, 256, gemm1_smem, s2>>>(x, W1, N);

    // CSR build on main stream
    k_prep<<<(N + 255) / 256, 256>>>(ei, E, N);
    k_count<<<(EQ + 255) / 256, 256>>>(ei, E);
    k_scan<<<NB1024, 1024>>>(N, E);
    cudaEventRecord(ev_scan, 0);

    // side stream: scale1 after scan (overlaps with scatter on main stream)
    cudaStreamWaitEvent(s2, ev_scan, 0);
    k_scale1<<<(N * 4 + 255) / 256, 256, 0, s2>>>(N);
    cudaEventRecord(ev_sc1, s2);

    k_scatter<<<(EQ + 255) / 256, 256>>>(ei, E);
    cudaStreamWaitEvent(0, ev_sc1, 0);

    // serial tail (overlap experiments regressed; keep this structure)
    k_agg1<<<(N + 7) / 8, 256>>>(b1, N);
    k_gemm2<<<(N + 63) / 64, 256>>>(W2, N);
    k_agg2<<<(N + 7) / 8, 256>>>(b2, N);
    k_decode<<<(EL * 8 + 255) / 256, 256>>>(eli, out, EL);

    cudaEventDestroy(ev_fork);
    cudaEventDestroy(ev_scan);
    cudaEventDestroy(ev_sc1);
    cudaStreamDestroy(s2);
}

// round 15
// speedup vs baseline: 1.0548x; 1.0036x over previous
#include <cuda_runtime.h>
#include <cuda_fp16.h>

// ---------------- fixed problem capacities (dataset is fixed) ----------------
#define NMAX 100000
#define EMAX 3200000
#define HDIM 64
#define ODIM 32
#define FDIM 128
#define XSTR 65    // padded fp32 [k][n] stride (gemm2)
#define HPAD 68    // padded half2/uint stride (=136 halves) for tensor gemm smem

// ---------------- device scratch (no allocations allowed) ----------------
__device__ int   g_is32;                              // 1 if edge indices are int32
__device__ int   g_ecnt[NMAX];                        // in-degree (no self loop)
__device__ int   g_ptr[NMAX + 1];                     // CSR offsets
__device__ unsigned long long g_scanstate[128];       // lookback: (flag<<32)|sum
__device__ float g_dinv[NMAX];                        // 1/sqrt(deg+1)
__device__ __align__(16) int     g_rank[EMAX];        // per-edge rank within dst
__device__ __align__(16) int     g_rows[EMAX];        // CSR adjacency: src per slot
__device__ __align__(16) __half2 g_s1h[NMAX * 32];    // fp16 dinv*(x@W1): 64 vals/node
__device__ __align__(16) __half2 g_z1h[NMAX * 32];    // fp16 relu layer-1 output
__device__ __align__(16) __half  g_s2h[NMAX * ODIM];  // fp16 dinv*(z1@W2): 32 vals/node
__device__ __align__(16) float   g_z2[NMAX * ODIM];   // layer-2 output (fp32)

__device__ __forceinline__ int edge_at(const void* p, long long j, int is32) {
    if (is32) return ((const int*)p)[j];
    return (int)((const long long*)p)[j];
}
__device__ __forceinline__ unsigned int pack_h2(float a, float b) {
    __half2 h = __floats2half2_rn(a, b);
    return *reinterpret_cast<unsigned int*>(&h);
}

// ---------------- prep: dtype detect + zero counters/flags ----------------
__global__ void k_prep(const void* ei, int E, int N) {
    int i = blockIdx.x * blockDim.x + threadIdx.x;
    if (i < N) g_ecnt[i] = 0;
    if (i < 128) g_scanstate[i] = 0ull;
    if (blockIdx.x == 0) {
        __shared__ int bad;
        if (threadIdx.x == 0) bad = 0;
        __syncthreads();
        int n = (2 * E < 256) ? 2 * E : 256;
        if (threadIdx.x < n) {
            long long v = ((const long long*)ei)[threadIdx.x];
            if (v < 0 || v >= NMAX) atomicOr(&bad, 1);
        }
        __syncthreads();
        if (threadIdx.x == 0) g_is32 = bad;
    }
}

// ------- count: 4 edges/thread; also records per-edge rank within its dst -------
__global__ void k_count(const void* __restrict__ ei, int E) {
    int q = blockIdx.x * blockDim.x + threadIdx.x;
    int e0 = q * 4;
    if (e0 >= E) return;
    int is32 = g_is32;
    if (e0 + 4 <= E) {
        int4 c;
        if (is32) {
            c = *(const int4*)((const int*)ei + E + e0);
        } else {
            const longlong2* p = (const longlong2*)((const long long*)ei + E + e0);
            longlong2 a = p[0], b = p[1];
            c = make_int4((int)a.x, (int)a.y, (int)b.x, (int)b.y);
        }
        int4 rk;
        rk.x = atomicAdd(&g_ecnt[c.x], 1);
        rk.y = atomicAdd(&g_ecnt[c.y], 1);
        rk.z = atomicAdd(&g_ecnt[c.z], 1);
        rk.w = atomicAdd(&g_ecnt[c.w], 1);
        *(int4*)(g_rank + e0) = rk;
    } else {
        for (int e = e0; e < E; e++) {
            int cc = edge_at(ei, (long long)E + e, is32);
            g_rank[e] = atomicAdd(&g_ecnt[cc], 1);
        }
    }
}

// ---- single-pass exclusive scan: warp scan + warp-parallel decoupled lookback ----
__global__ void k_scan(int N, int E) {
    __shared__ int wsum[32];
    __shared__ int s_prefix;
    int t = threadIdx.x, b = blockIdx.x;
    int lane = t & 31, wid = t >> 5;
    int i = b * 1024 + t;
    int v = (i < N) ? g_ecnt[i] : 0;

    int s = v;
#pragma unroll
    for (int o = 1; o < 32; o <<= 1) {
        int y = __shfl_up_sync(0xffffffffu, s, o);
        if (lane >= o) s += y;
    }
    if (lane == 31) wsum[wid] = s;
    __syncthreads();
    if (wid == 0) {
        int ws = wsum[lane];
#pragma unroll
        for (int o = 1; o < 32; o <<= 1) {
            int y = __shfl_up_sync(0xffffffffu, ws, o);
            if (lane >= o) ws += y;
        }
        wsum[lane] = ws;
    }
    __syncthreads();
    int incl = s + (wid ? wsum[wid - 1] : 0);
    int btotal = wsum[31];

    if (wid == 0) {
        if (b == 0) {
            if (lane == 0) {
                atomicExch(&g_scanstate[0], (2ull << 32) | (unsigned int)btotal);
                s_prefix = 0;
            }
        } else {
            if (lane == 0)
                atomicExch(&g_scanstate[b], (1ull << 32) | (unsigned int)btotal);
            __syncwarp();
            long long pref = 0;
            int base = b;
            while (true) {
                int idx = base - 32 + lane;
                bool valid = idx >= 0;
                unsigned long long st = 0;
                if (valid) {
                    do { st = atomicAdd(&g_scanstate[idx], 0ull); } while ((st >> 32) == 0);
                }
                unsigned m = __ballot_sync(0xffffffffu, valid && (st >> 32) == 2ull);
                int cut = m ? (31 - __clz(m)) : 32;
                bool contrib = valid && (cut == 32 || lane >= cut);
                long long c = contrib ? (long long)(st & 0xffffffffull) : 0;
#pragma unroll
                for (int o = 16; o; o >>= 1) c += __shfl_xor_sync(0xffffffffu, c, o);
                pref += c;
                if (cut != 32) break;
                base -= 32;
            }
            if (lane == 0) {
                atomicExch(&g_scanstate[b],
                           (2ull << 32) | (unsigned int)(pref + (long long)btotal));
                s_prefix = (int)pref;
            }
        }
    }
    __syncthreads();
    int p = s_prefix + incl - v;
    if (i < N) {
        g_ptr[i] = p;
        g_dinv[i] = rsqrtf((float)(g_ecnt[i] + 1));
    }
    if (i == 0) g_ptr[N] = E;
}

// ------- scatter (atomic-free fill): g_rows[ptr[c]+rank] = r -------
__global__ void k_scatter(const void* __restrict__ ei, int E) {
    int q = blockIdx.x * blockDim.x + threadIdx.x;
    int e0 = q * 4;
    if (e0 >= E) return;
    int is32 = g_is32;
    if (e0 + 4 <= E) {
        int4 r, c;
        if (is32) {
            r = *(const int4*)((const int*)ei + e0);
            c = *(const int4*)((const int*)ei + E + e0);
        } else {
            const longlong2* rp = (const longlong2*)((const long long*)ei + e0);
            const longlong2* cp = (const longlong2*)((const long long*)ei + E + e0);
            longlong2 ra = rp[0], rb = rp[1], ca = cp[0], cb = cp[1];
            r = make_int4((int)ra.x, (int)ra.y, (int)rb.x, (int)rb.y);
            c = make_int4((int)ca.x, (int)ca.y, (int)cb.x, (int)cb.y);
        }
        int4 rk = *(const int4*)(g_rank + e0);
        g_rows[g_ptr[c.x] + rk.x] = r.x;
        g_rows[g_ptr[c.y] + rk.y] = r.y;
        g_rows[g_ptr[c.z] + rk.z] = r.z;
        g_rows[g_ptr[c.w] + rk.w] = r.w;
    } else {
        for (int e = e0; e < E; e++) {
            int rr = edge_at(ei, e, is32);
            int cc = edge_at(ei, (long long)E + e, is32);
            g_rows[g_ptr[cc] + g_rank[e]] = rr;
        }
    }
}

// ---------------- GEMM1 (tensor cores): s1h_raw = fp16( x @ W1 ) ----------------
__global__ __launch_bounds__(256) void k_gemm1(const float* __restrict__ x,
                                               const float* __restrict__ W1, int N) {
    extern __shared__ unsigned int smu[];
    unsigned int* xh = smu;
    unsigned int* wh = smu + 128 * HPAD;
    __half* whh = (__half*)wh;
    int t = threadIdx.x;

    for (int i = t; i < FDIM * HDIM; i += 256) {
        int k = i >> 6, n = i & 63;
        whh[n * (2 * HPAD) + k] = __float2half_rn(W1[i]);
    }
    int node0 = blockIdx.x * 128;
    const float4* x4 = (const float4*)x;
    for (int i = t; i < 128 * 32; i += 256) {
        int nd = i >> 5, kq = i & 31;
        int gn = node0 + nd;
        float4 v = (gn < N) ? x4[(size_t)gn * 32 + kq] : make_float4(0.f, 0.f, 0.f, 0.f);
        xh[nd * HPAD + kq * 2]     = pack_h2(v.x, v.y);
        xh[nd * HPAD + kq * 2 + 1] = pack_h2(v.z, v.w);
    }
    __syncthreads();

    int wid = t >> 5, lane = t & 31;
    int g = lane >> 2, tq = lane & 3;
    int nodeW = wid * 16;

    unsigned int A[8][4];
#pragma unroll
    for (int ks = 0; ks < 8; ks++) {
        int base0 = (nodeW + g) * HPAD + ks * 8 + tq;
        int base1 = (nodeW + g + 8) * HPAD + ks * 8 + tq;
        A[ks][0] = xh[base0];
        A[ks][1] = xh[base1];
        A[ks][2] = xh[base0 + 4];
        A[ks][3] = xh[base1 + 4];
    }

    float acc[8][4];
#pragma unroll
    for (int nt = 0; nt < 8; nt++)
#pragma unroll
        for (int j = 0; j < 4; j++) acc[nt][j] = 0.f;

#pragma unroll
    for (int nt = 0; nt < 8; nt++) {
        int brow = (nt * 8 + g) * HPAD + tq;
#pragma unroll
        for (int ks = 0; ks < 8; ks++) {
            unsigned int b0 = wh[brow + ks * 8];
            unsigned int b1 = wh[brow + ks * 8 + 4];
            asm volatile(
                "mma.sync.aligned.m16n8k16.row.col.f32.f16.f16.f32 "
                "{%0,%1,%2,%3}, {%4,%5,%6,%7}, {%8,%9}, {%0,%1,%2,%3};"
                : "+f"(acc[nt][0]), "+f"(acc[nt][1]), "+f"(acc[nt][2]), "+f"(acc[nt][3])
                : "r"(A[ks][0]), "r"(A[ks][1]), "r"(A[ks][2]), "r"(A[ks][3]),
                  "r"(b0), "r"(b1));
        }
    }

    int gn0 = node0 + nodeW + g;
    int gn1 = gn0 + 8;
    unsigned int* s1u = (unsigned int*)g_s1h;
#pragma unroll
    for (int nt = 0; nt < 8; nt++) {
        int ch = (nt * 8 + tq * 2) >> 1;
        if (gn0 < N) s1u[(size_t)gn0 * 32 + ch] = pack_h2(acc[nt][0], acc[nt][1]);
        if (gn1 < N) s1u[(size_t)gn1 * 32 + ch] = pack_h2(acc[nt][2], acc[nt][3]);
    }
}

// ---------------- scale1: s1h *= dinv ----------------
__global__ void k_scale1(int N) {
    int tid = blockIdx.x * blockDim.x + threadIdx.x;
    int node = tid >> 2, q = tid & 3;
    if (node >= N) return;
    float d = g_dinv[node];
    uint4* p = (uint4*)g_s1h + (size_t)node * 8 + q * 2;
#pragma unroll
    for (int u = 0; u < 2; u++) {
        uint4 v = p[u];
        unsigned int* vi = (unsigned int*)&v;
#pragma unroll
        for (int j = 0; j < 4; j++) {
            float2 f = __half22float2(*(__half2*)&vi[j]);
            vi[j] = pack_h2(d * f.x, d * f.y);
        }
        p[u] = v;
    }
}

// ---- agg1: 8 lanes x uint4(16B) per 128B row; 4 edge-parities, 16 edges/iter ----
__global__ __launch_bounds__(256) void k_agg1(const float* __restrict__ b1, int N) {
    int w = (blockIdx.x * blockDim.x + threadIdx.x) >> 5;
    int lane = threadIdx.x & 31;
    if (w >= N) return;
    int h = lane & 7, sub = lane >> 3;
    int beg = g_ptr[w], end = g_ptr[w + 1];
    const uint4* s1 = (const uint4*)g_s1h;

    float a0 = 0.f, a1 = 0.f, a2 = 0.f, a3 = 0.f;
    float a4 = 0.f, a5 = 0.f, a6 = 0.f, a7 = 0.f;
    int nE = end - beg;
    int nChunk = nE >> 4;
    for (int c = 0; c < nChunk; c++) {
        int base = beg + c * 16 + sub;
        int r0 = g_rows[base],     r1 = g_rows[base + 4];
        int r2 = g_rows[base + 8], r3 = g_rows[base + 12];
        uint4 u0 = s1[(size_t)r0 * 8 + h];
        uint4 u1 = s1[(size_t)r1 * 8 + h];
        uint4 u2 = s1[(size_t)r2 * 8 + h];
        uint4 u3 = s1[(size_t)r3 * 8 + h];
        float2 f;
        f = __half22float2(*(__half2*)&u0.x); a0 += f.x; a1 += f.y;
        f = __half22float2(*(__half2*)&u0.y); a2 += f.x; a3 += f.y;
        f = __half22float2(*(__half2*)&u0.z); a4 += f.x; a5 += f.y;
        f = __half22float2(*(__half2*)&u0.w); a6 += f.x; a7 += f.y;
        f = __half22float2(*(__half2*)&u1.x); a0 += f.x; a1 += f.y;
        f = __half22float2(*(__half2*)&u1.y); a2 += f.x; a3 += f.y;
        f = __half22float2(*(__half2*)&u1.z); a4 += f.x; a5 += f.y;
        f = __half22float2(*(__half2*)&u1.w); a6 += f.x; a7 += f.y;
        f = __half22float2(*(__half2*)&u2.x); a0 += f.x; a1 += f.y;
        f = __half22float2(*(__half2*)&u2.y); a2 += f.x; a3 += f.y;
        f = __half22float2(*(__half2*)&u2.z); a4 += f.x; a5 += f.y;
        f = __half22float2(*(__half2*)&u2.w); a6 += f.x; a7 += f.y;
        f = __half22float2(*(__half2*)&u3.x); a0 += f.x; a1 += f.y;
        f = __half22float2(*(__half2*)&u3.y); a2 += f.x; a3 += f.y;
        f = __half22float2(*(__half2*)&u3.z); a4 += f.x; a5 += f.y;
        f = __half22float2(*(__half2*)&u3.w); a6 += f.x; a7 += f.y;
    }
    for (int i = beg + nChunk * 16 + sub; i < end; i += 4) {
        uint4 u = s1[(size_t)g_rows[i] * 8 + h];
        float2 f;
        f = __half22float2(*(__half2*)&u.x); a0 += f.x; a1 += f.y;
        f = __half22float2(*(__half2*)&u.y); a2 += f.x; a3 += f.y;
        f = __half22float2(*(__half2*)&u.z); a4 += f.x; a5 += f.y;
        f = __half22float2(*(__half2*)&u.w); a6 += f.x; a7 += f.y;
    }
#pragma unroll
    for (int o = 8; o <= 16; o <<= 1) {
        a0 += __shfl_xor_sync(0xffffffffu, a0, o);
        a1 += __shfl_xor_sync(0xffffffffu, a1, o);
        a2 += __shfl_xor_sync(0xffffffffu, a2, o);
        a3 += __shfl_xor_sync(0xffffffffu, a3, o);
        a4 += __shfl_xor_sync(0xffffffffu, a4, o);
        a5 += __shfl_xor_sync(0xffffffffu, a5, o);
        a6 += __shfl_xor_sync(0xffffffffu, a6, o);
        a7 += __shfl_xor_sync(0xffffffffu, a7, o);
    }
    if (sub == 0) {
        uint4 us = s1[(size_t)w * 8 + h];
        float2 f;
        f = __half22float2(*(__half2*)&us.x); a0 += f.x; a1 += f.y;
        f = __half22float2(*(__half2*)&us.y); a2 += f.x; a3 += f.y;
        f = __half22float2(*(__half2*)&us.z); a4 += f.x; a5 += f.y;
        f = __half22float2(*(__half2*)&us.w); a6 += f.x; a7 += f.y;
        float d = g_dinv[w];
        float4 b0 = ((const float4*)b1)[h * 2];
        float4 b2v = ((const float4*)b1)[h * 2 + 1];
        uint4 zz;
        zz.x = pack_h2(fmaxf(fmaf(d, a0, b0.x), 0.f),  fmaxf(fmaf(d, a1, b0.y), 0.f));
        zz.y = pack_h2(fmaxf(fmaf(d, a2, b0.z), 0.f),  fmaxf(fmaf(d, a3, b0.w), 0.f));
        zz.z = pack_h2(fmaxf(fmaf(d, a4, b2v.x), 0.f), fmaxf(fmaf(d, a5, b2v.y), 0.f));
        zz.w = pack_h2(fmaxf(fmaf(d, a6, b2v.z), 0.f), fmaxf(fmaf(d, a7, b2v.w), 0.f));
        ((uint4*)g_z1h)[(size_t)w * 8 + h] = zz;
    }
}

// ------ GEMM2: s2h = fp16( dinv * (z1h @ W2) )   [N,64]x[64,32], z1 in fp16 ------
__global__ __launch_bounds__(256) void k_gemm2(const float* __restrict__ W2, int N) {
    __shared__ float Ws[HDIM * ODIM];
    __shared__ float zs[HDIM * XSTR];
    int t = threadIdx.x;
    for (int i = t; i < HDIM * ODIM; i += 256) Ws[i] = W2[i];

    int node0 = blockIdx.x * 64;
    int lane = t & 31, wrp = t >> 5;
    const unsigned int* z1u = (const unsigned int*)g_z1h;
#pragma unroll
    for (int rep = 0; rep < 8; rep++) {
        int n = wrp * 8 + rep;
        int gn = node0 + n;
        unsigned int u = (gn < N) ? z1u[(size_t)gn * 32 + lane] : 0u;
        float2 f = __half22float2(*(__half2*)&u);
        zs[(2 * lane) * XSTR + n]     = f.x;
        zs[(2 * lane + 1) * XSTR + n] = f.y;
    }
    __syncthreads();

    int n = t & 63;
    int og = t >> 6;
    float acc[8];
#pragma unroll
    for (int i = 0; i < 8; i++) acc[i] = 0.f;
    const float4* Ws4 = (const float4*)Ws;
#pragma unroll 4
    for (int k = 0; k < HDIM; k++) {
        float xv = zs[k * XSTR + n];
        float4 w0 = Ws4[k * 8 + og * 2];
        float4 w1 = Ws4[k * 8 + og * 2 + 1];
        acc[0] = fmaf(xv, w0.x, acc[0]); acc[1] = fmaf(xv, w0.y, acc[1]);
        acc[2] = fmaf(xv, w0.z, acc[2]); acc[3] = fmaf(xv, w0.w, acc[3]);
        acc[4] = fmaf(xv, w1.x, acc[4]); acc[5] = fmaf(xv, w1.y, acc[5]);
        acc[6] = fmaf(xv, w1.z, acc[6]); acc[7] = fmaf(xv, w1.w, acc[7]);
    }
    int gn = node0 + n;
    if (gn < N) {
        float d = g_dinv[gn];
        unsigned int p[4];
#pragma unroll
        for (int j = 0; j < 4; j++) p[j] = pack_h2(d * acc[2 * j], d * acc[2 * j + 1]);
        *(uint4*)(g_s2h + (size_t)gn * ODIM + og * 8) = make_uint4(p[0], p[1], p[2], p[3]);
    }
}

// ---- agg2: 8 lanes x uint2(8B) per 64B row; 4 edge-parities, 16 edges/iter ----
__global__ __launch_bounds__(256) void k_agg2(const float* __restrict__ b2, int N) {
    int w = (blockIdx.x * blockDim.x + threadIdx.x) >> 5;
    int lane = threadIdx.x & 31;
    if (w >= N) return;
    int h = lane & 7, sub = lane >> 3;
    int beg = g_ptr[w], end = g_ptr[w + 1];
    const uint2* s2 = (const uint2*)g_s2h;

    float a0 = 0.f, a1 = 0.f, a2 = 0.f, a3 = 0.f;
    int nE = end - beg;
    int nChunk = nE >> 4;
    for (int c = 0; c < nChunk; c++) {
        int base = beg + c * 16 + sub;
        int r0 = g_rows[base],     r1 = g_rows[base + 4];
        int r2 = g_rows[base + 8], r3 = g_rows[base + 12];
        uint2 u0 = s2[(size_t)r0 * 8 + h];
        uint2 u1 = s2[(size_t)r1 * 8 + h];
        uint2 u2 = s2[(size_t)r2 * 8 + h];
        uint2 u3 = s2[(size_t)r3 * 8 + h];
        float2 f;
        f = __half22float2(*(__half2*)&u0.x); a0 += f.x; a1 += f.y;
        f = __half22float2(*(__half2*)&u0.y); a2 += f.x; a3 += f.y;
        f = __half22float2(*(__half2*)&u1.x); a0 += f.x; a1 += f.y;
        f = __half22float2(*(__half2*)&u1.y); a2 += f.x; a3 += f.y;
        f = __half22float2(*(__half2*)&u2.x); a0 += f.x; a1 += f.y;
        f = __half22float2(*(__half2*)&u2.y); a2 += f.x; a3 += f.y;
        f = __half22float2(*(__half2*)&u3.x); a0 += f.x; a1 += f.y;
        f = __half22float2(*(__half2*)&u3.y); a2 += f.x; a3 += f.y;
    }
    for (int i = beg + nChunk * 16 + sub; i < end; i += 4) {
        uint2 u = s2[(size_t)g_rows[i] * 8 + h];
        float2 f;
        f = __half22float2(*(__half2*)&u.x); a0 += f.x; a1 += f.y;
        f = __half22float2(*(__half2*)&u.y); a2 += f.x; a3 += f.y;
    }
#pragma unroll
    for (int o = 8; o <= 16; o <<= 1) {
        a0 += __shfl_xor_sync(0xffffffffu, a0, o);
        a1 += __shfl_xor_sync(0xffffffffu, a1, o);
        a2 += __shfl_xor_sync(0xffffffffu, a2, o);
        a3 += __shfl_xor_sync(0xffffffffu, a3, o);
    }
    if (sub == 0) {
        uint2 us = s2[(size_t)w * 8 + h];
        float2 f;
        f = __half22float2(*(__half2*)&us.x); a0 += f.x; a1 += f.y;
        f = __half22float2(*(__half2*)&us.y); a2 += f.x; a3 += f.y;
        float d = g_dinv[w];
        float4 bb = ((const float4*)b2)[h];
        float4 z;
        z.x = fmaf(d, a0, bb.x);
        z.y = fmaf(d, a1, bb.y);
        z.z = fmaf(d, a2, bb.z);
        z.w = fmaf(d, a3, bb.w);
        ((float4*)g_z2)[(size_t)w * 8 + h] = z;
    }
}

// ---------------- decode: out[p] = dot(z2[a], z2[b]) over 32 dims ----------------
__global__ __launch_bounds__(256) void k_decode(const void* __restrict__ eli,
                                                float* __restrict__ out, int EL) {
    int t = blockIdx.x * blockDim.x + threadIdx.x;
    int p = t >> 3;
    int j = t & 7;
    if (p >= EL) return;
    int is32 = g_is32;
    int a = edge_at(eli, p, is32);
    int b = edge_at(eli, (long long)EL + p, is32);
    float4 va = ((const float4*)g_z2)[a * 8 + j];
    float4 vb = ((const float4*)g_z2)[b * 8 + j];
    float s = va.x * vb.x + va.y * vb.y + va.z * vb.z + va.w * vb.w;
    s += __shfl_down_sync(0xffffffffu, s, 4, 8);
    s += __shfl_down_sync(0xffffffffu, s, 2, 8);
    s += __shfl_down_sync(0xffffffffu, s, 1, 8);
    if (j == 0) out[p] = s;
}

// ---------------- launch ----------------
extern "C" void kernel_launch(void* const* d_in, const int* in_sizes, int n_in,
                              void* d_out, int out_size) {
    const float* x   = (const float*)d_in[0];
    const float* W1  = (const float*)d_in[1];
    const float* b1  = (const float*)d_in[2];
    const float* W2  = (const float*)d_in[3];
    const float* b2  = (const float*)d_in[4];
    const void*  ei  = d_in[5];
    const void*  eli = d_in[6];

    int H  = in_sizes[2];                 // 64
    int F  = in_sizes[1] / H;             // 128
    int N  = in_sizes[0] / F;             // 100000
    int E  = in_sizes[5] / 2;             // 3200000
    int EL = in_sizes[6] / 2;             // 200000
    float* out = (float*)d_out;

    int NB1024 = (N + 1023) / 1024;
    int EQ = (E + 3) / 4;
    int gemm1_smem = (128 * HPAD + 64 * HPAD) * sizeof(unsigned int);
    cudaFuncSetAttribute(k_gemm1, cudaFuncAttributeMaxDynamicSharedMemorySize, gemm1_smem);

    cudaStream_t s2;
    cudaStreamCreateWithFlags(&s2, cudaStreamNonBlocking);
    cudaEvent_t ev_fork, ev_scan, ev_sc1;
    cudaEventCreateWithFlags(&ev_fork, cudaEventDisableTiming);
    cudaEventCreateWithFlags(&ev_scan, cudaEventDisableTiming);
    cudaEventCreateWithFlags(&ev_sc1, cudaEventDisableTiming);

    // fork: raw gemm1 depends on nothing
    cudaEventRecord(ev_fork, 0);
    cudaStreamWaitEvent(s2, ev_fork, 0);
    k_gemm1<<<(N + 127) / 128, 256, gemm1_smem, s2>>>(x, W1, N);

    // CSR build on main stream
    k_prep<<<(N + 255) / 256, 256>>>(ei, E, N);
    k_count<<<(EQ + 255) / 256, 256>>>(ei, E);
    k_scan<<<NB1024, 1024>>>(N, E);
    cudaEventRecord(ev_scan, 0);

    // side stream: scale1 after scan (overlaps with scatter on main stream)
    cudaStreamWaitEvent(s2, ev_scan, 0);
    k_scale1<<<(N * 4 + 255) / 256, 256, 0, s2>>>(N);
    cudaEventRecord(ev_sc1, s2);

    k_scatter<<<(EQ + 255) / 256, 256>>>(ei, E);
    cudaStreamWaitEvent(0, ev_sc1, 0);

    // serial tail (overlap experiments regressed; keep this structure)
    k_agg1<<<(N + 7) / 8, 256>>>(b1, N);
    k_gemm2<<<(N + 63) / 64, 256>>>(W2, N);
    k_agg2<<<(N + 7) / 8, 256>>>(b2, N);
    k_decode<<<(EL * 8 + 255) / 256, 256>>>(eli, out, EL);

    cudaEventDestroy(ev_fork);
    cudaEventDestroy(ev_scan);
    cudaEventDestroy(ev_sc1);
    cudaStreamDestroy(s2);
}

// round 16
// speedup vs baseline: 1.0609x; 1.0057x over previous
#include <cuda_runtime.h>
#include <cuda_fp16.h>

// ---------------- fixed problem capacities (dataset is fixed) ----------------
#define NMAX 100000
#define EMAX 3200000
#define HDIM 64
#define ODIM 32
#define FDIM 128
#define XSTR 65    // padded fp32 [k][n] stride (gemm2)
#define HPAD 68    // padded half2/uint stride (=136 halves) for tensor gemm smem

// ---------------- device scratch (no allocations allowed) ----------------
__device__ int   g_is32;                              // 1 if edge indices are int32
__device__ int   g_ecnt[NMAX];                        // in-degree (no self loop)
__device__ int   g_ptr[NMAX + 1];                     // CSR offsets
__device__ unsigned long long g_scanstate[128];       // lookback: (flag<<32)|sum
__device__ float g_dinv[NMAX];                        // 1/sqrt(deg+1)
__device__ __align__(16) int     g_rank[EMAX];        // per-edge rank within dst
__device__ __align__(16) int     g_rows[EMAX];        // CSR adjacency: src per slot
__device__ __align__(16) __half2 g_s1h[NMAX * 32];    // fp16 dinv*(x@W1): 64 vals/node
__device__ __align__(16) __half2 g_z1h[NMAX * 32];    // fp16 relu layer-1 output
__device__ __align__(16) __half  g_s2h[NMAX * ODIM];  // fp16 dinv*(z1@W2): 32 vals/node
__device__ __align__(16) __half2 g_z2h[NMAX * 16];    // fp16 layer-2 output

__device__ __forceinline__ int edge_at(const void* p, long long j, int is32) {
    if (is32) return ((const int*)p)[j];
    return (int)((const long long*)p)[j];
}
__device__ __forceinline__ unsigned int pack_h2(float a, float b) {
    __half2 h = __floats2half2_rn(a, b);
    return *reinterpret_cast<unsigned int*>(&h);
}

// ---------------- prep: dtype detect + zero counters/flags ----------------
__global__ void k_prep(const void* ei, int E, int N) {
    int i = blockIdx.x * blockDim.x + threadIdx.x;
    if (i < N) g_ecnt[i] = 0;
    if (i < 128) g_scanstate[i] = 0ull;
    if (blockIdx.x == 0) {
        __shared__ int bad;
        if (threadIdx.x == 0) bad = 0;
        __syncthreads();
        int n = (2 * E < 256) ? 2 * E : 256;
        if (threadIdx.x < n) {
            long long v = ((const long long*)ei)[threadIdx.x];
            if (v < 0 || v >= NMAX) atomicOr(&bad, 1);
        }
        __syncthreads();
        if (threadIdx.x == 0) g_is32 = bad;
    }
}

// ------- count: 4 edges/thread; also records per-edge rank within its dst -------
__global__ void k_count(const void* __restrict__ ei, int E) {
    int q = blockIdx.x * blockDim.x + threadIdx.x;
    int e0 = q * 4;
    if (e0 >= E) return;
    int is32 = g_is32;
    if (e0 + 4 <= E) {
        int4 c;
        if (is32) {
            c = *(const int4*)((const int*)ei + E + e0);
        } else {
            const longlong2* p = (const longlong2*)((const long long*)ei + E + e0);
            longlong2 a = p[0], b = p[1];
            c = make_int4((int)a.x, (int)a.y, (int)b.x, (int)b.y);
        }
        int4 rk;
        rk.x = atomicAdd(&g_ecnt[c.x], 1);
        rk.y = atomicAdd(&g_ecnt[c.y], 1);
        rk.z = atomicAdd(&g_ecnt[c.z], 1);
        rk.w = atomicAdd(&g_ecnt[c.w], 1);
        *(int4*)(g_rank + e0) = rk;
    } else {
        for (int e = e0; e < E; e++) {
            int cc = edge_at(ei, (long long)E + e, is32);
            g_rank[e] = atomicAdd(&g_ecnt[cc], 1);
        }
    }
}

// ---- single-pass exclusive scan: warp scan + warp-parallel decoupled lookback ----
__global__ void k_scan(int N, int E) {
    __shared__ int wsum[32];
    __shared__ int s_prefix;
    int t = threadIdx.x, b = blockIdx.x;
    int lane = t & 31, wid = t >> 5;
    int i = b * 1024 + t;
    int v = (i < N) ? g_ecnt[i] : 0;

    int s = v;
#pragma unroll
    for (int o = 1; o < 32; o <<= 1) {
        int y = __shfl_up_sync(0xffffffffu, s, o);
        if (lane >= o) s += y;
    }
    if (lane == 31) wsum[wid] = s;
    __syncthreads();
    if (wid == 0) {
        int ws = wsum[lane];
#pragma unroll
        for (int o = 1; o < 32; o <<= 1) {
            int y = __shfl_up_sync(0xffffffffu, ws, o);
            if (lane >= o) ws += y;
        }
        wsum[lane] = ws;
    }
    __syncthreads();
    int incl = s + (wid ? wsum[wid - 1] : 0);
    int btotal = wsum[31];

    if (wid == 0) {
        if (b == 0) {
            if (lane == 0) {
                atomicExch(&g_scanstate[0], (2ull << 32) | (unsigned int)btotal);
                s_prefix = 0;
            }
        } else {
            if (lane == 0)
                atomicExch(&g_scanstate[b], (1ull << 32) | (unsigned int)btotal);
            __syncwarp();
            long long pref = 0;
            int base = b;
            while (true) {
                int idx = base - 32 + lane;
                bool valid = idx >= 0;
                unsigned long long st = 0;
                if (valid) {
                    do { st = atomicAdd(&g_scanstate[idx], 0ull); } while ((st >> 32) == 0);
                }
                unsigned m = __ballot_sync(0xffffffffu, valid && (st >> 32) == 2ull);
                int cut = m ? (31 - __clz(m)) : 32;
                bool contrib = valid && (cut == 32 || lane >= cut);
                long long c = contrib ? (long long)(st & 0xffffffffull) : 0;
#pragma unroll
                for (int o = 16; o; o >>= 1) c += __shfl_xor_sync(0xffffffffu, c, o);
                pref += c;
                if (cut != 32) break;
                base -= 32;
            }
            if (lane == 0) {
                atomicExch(&g_scanstate[b],
                           (2ull << 32) | (unsigned int)(pref + (long long)btotal));
                s_prefix = (int)pref;
            }
        }
    }
    __syncthreads();
    int p = s_prefix + incl - v;
    if (i < N) {
        g_ptr[i] = p;
        g_dinv[i] = rsqrtf((float)(g_ecnt[i] + 1));
    }
    if (i == 0) g_ptr[N] = E;
}

// ------- scatter (atomic-free fill): g_rows[ptr[c]+rank] = r -------
__global__ void k_scatter(const void* __restrict__ ei, int E) {
    int q = blockIdx.x * blockDim.x + threadIdx.x;
    int e0 = q * 4;
    if (e0 >= E) return;
    int is32 = g_is32;
    if (e0 + 4 <= E) {
        int4 r, c;
        if (is32) {
            r = *(const int4*)((const int*)ei + e0);
            c = *(const int4*)((const int*)ei + E + e0);
        } else {
            const longlong2* rp = (const longlong2*)((const long long*)ei + e0);
            const longlong2* cp = (const longlong2*)((const long long*)ei + E + e0);
            longlong2 ra = rp[0], rb = rp[1], ca = cp[0], cb = cp[1];
            r = make_int4((int)ra.x, (int)ra.y, (int)rb.x, (int)rb.y);
            c = make_int4((int)ca.x, (int)ca.y, (int)cb.x, (int)cb.y);
        }
        int4 rk = *(const int4*)(g_rank + e0);
        g_rows[g_ptr[c.x] + rk.x] = r.x;
        g_rows[g_ptr[c.y] + rk.y] = r.y;
        g_rows[g_ptr[c.z] + rk.z] = r.z;
        g_rows[g_ptr[c.w] + rk.w] = r.w;
    } else {
        for (int e = e0; e < E; e++) {
            int rr = edge_at(ei, e, is32);
            int cc = edge_at(ei, (long long)E + e, is32);
            g_rows[g_ptr[cc] + g_rank[e]] = rr;
        }
    }
}

// ---------------- GEMM1 (tensor cores): s1h_raw = fp16( x @ W1 ) ----------------
__global__ __launch_bounds__(256) void k_gemm1(const float* __restrict__ x,
                                               const float* __restrict__ W1, int N) {
    extern __shared__ unsigned int smu[];
    unsigned int* xh = smu;
    unsigned int* wh = smu + 128 * HPAD;
    __half* whh = (__half*)wh;
    int t = threadIdx.x;

    for (int i = t; i < FDIM * HDIM; i += 256) {
        int k = i >> 6, n = i & 63;
        whh[n * (2 * HPAD) + k] = __float2half_rn(W1[i]);
    }
    int node0 = blockIdx.x * 128;
    const float4* x4 = (const float4*)x;
    for (int i = t; i < 128 * 32; i += 256) {
        int nd = i >> 5, kq = i & 31;
        int gn = node0 + nd;
        float4 v = (gn < N) ? x4[(size_t)gn * 32 + kq] : make_float4(0.f, 0.f, 0.f, 0.f);
        xh[nd * HPAD + kq * 2]     = pack_h2(v.x, v.y);
        xh[nd * HPAD + kq * 2 + 1] = pack_h2(v.z, v.w);
    }
    __syncthreads();

    int wid = t >> 5, lane = t & 31;
    int g = lane >> 2, tq = lane & 3;
    int nodeW = wid * 16;

    unsigned int A[8][4];
#pragma unroll
    for (int ks = 0; ks < 8; ks++) {
        int base0 = (nodeW + g) * HPAD + ks * 8 + tq;
        int base1 = (nodeW + g + 8) * HPAD + ks * 8 + tq;
        A[ks][0] = xh[base0];
        A[ks][1] = xh[base1];
        A[ks][2] = xh[base0 + 4];
        A[ks][3] = xh[base1 + 4];
    }

    float acc[8][4];
#pragma unroll
    for (int nt = 0; nt < 8; nt++)
#pragma unroll
        for (int j = 0; j < 4; j++) acc[nt][j] = 0.f;

#pragma unroll
    for (int nt = 0; nt < 8; nt++) {
        int brow = (nt * 8 + g) * HPAD + tq;
#pragma unroll
        for (int ks = 0; ks < 8; ks++) {
            unsigned int b0 = wh[brow + ks * 8];
            unsigned int b1 = wh[brow + ks * 8 + 4];
            asm volatile(
                "mma.sync.aligned.m16n8k16.row.col.f32.f16.f16.f32 "
                "{%0,%1,%2,%3}, {%4,%5,%6,%7}, {%8,%9}, {%0,%1,%2,%3};"
                : "+f"(acc[nt][0]), "+f"(acc[nt][1]), "+f"(acc[nt][2]), "+f"(acc[nt][3])
                : "r"(A[ks][0]), "r"(A[ks][1]), "r"(A[ks][2]), "r"(A[ks][3]),
                  "r"(b0), "r"(b1));
        }
    }

    int gn0 = node0 + nodeW + g;
    int gn1 = gn0 + 8;
    unsigned int* s1u = (unsigned int*)g_s1h;
#pragma unroll
    for (int nt = 0; nt < 8; nt++) {
        int ch = (nt * 8 + tq * 2) >> 1;
        if (gn0 < N) s1u[(size_t)gn0 * 32 + ch] = pack_h2(acc[nt][0], acc[nt][1]);
        if (gn1 < N) s1u[(size_t)gn1 * 32 + ch] = pack_h2(acc[nt][2], acc[nt][3]);
    }
}

// ---------------- scale1: s1h *= dinv ----------------
__global__ void k_scale1(int N) {
    int tid = blockIdx.x * blockDim.x + threadIdx.x;
    int node = tid >> 2, q = tid & 3;
    if (node >= N) return;
    float d = g_dinv[node];
    uint4* p = (uint4*)g_s1h + (size_t)node * 8 + q * 2;
#pragma unroll
    for (int u = 0; u < 2; u++) {
        uint4 v = p[u];
        unsigned int* vi = (unsigned int*)&v;
#pragma unroll
        for (int j = 0; j < 4; j++) {
            float2 f = __half22float2(*(__half2*)&vi[j]);
            vi[j] = pack_h2(d * f.x, d * f.y);
        }
        p[u] = v;
    }
}

// ---- agg1: 8 lanes x uint4(16B) per 128B row; 4 edge-parities, 16 edges/iter ----
__global__ __launch_bounds__(256) void k_agg1(const float* __restrict__ b1, int N) {
    int w = (blockIdx.x * blockDim.x + threadIdx.x) >> 5;
    int lane = threadIdx.x & 31;
    if (w >= N) return;
    int h = lane & 7, sub = lane >> 3;
    int beg = g_ptr[w], end = g_ptr[w + 1];
    const uint4* s1 = (const uint4*)g_s1h;

    float a0 = 0.f, a1 = 0.f, a2 = 0.f, a3 = 0.f;
    float a4 = 0.f, a5 = 0.f, a6 = 0.f, a7 = 0.f;
    int nE = end - beg;
    int nChunk = nE >> 4;
    for (int c = 0; c < nChunk; c++) {
        int base = beg + c * 16 + sub;
        int r0 = g_rows[base],     r1 = g_rows[base + 4];
        int r2 = g_rows[base + 8], r3 = g_rows[base + 12];
        uint4 u0 = s1[(size_t)r0 * 8 + h];
        uint4 u1 = s1[(size_t)r1 * 8 + h];
        uint4 u2 = s1[(size_t)r2 * 8 + h];
        uint4 u3 = s1[(size_t)r3 * 8 + h];
        float2 f;
        f = __half22float2(*(__half2*)&u0.x); a0 += f.x; a1 += f.y;
        f = __half22float2(*(__half2*)&u0.y); a2 += f.x; a3 += f.y;
        f = __half22float2(*(__half2*)&u0.z); a4 += f.x; a5 += f.y;
        f = __half22float2(*(__half2*)&u0.w); a6 += f.x; a7 += f.y;
        f = __half22float2(*(__half2*)&u1.x); a0 += f.x; a1 += f.y;
        f = __half22float2(*(__half2*)&u1.y); a2 += f.x; a3 += f.y;
        f = __half22float2(*(__half2*)&u1.z); a4 += f.x; a5 += f.y;
        f = __half22float2(*(__half2*)&u1.w); a6 += f.x; a7 += f.y;
        f = __half22float2(*(__half2*)&u2.x); a0 += f.x; a1 += f.y;
        f = __half22float2(*(__half2*)&u2.y); a2 += f.x; a3 += f.y;
        f = __half22float2(*(__half2*)&u2.z); a4 += f.x; a5 += f.y;
        f = __half22float2(*(__half2*)&u2.w); a6 += f.x; a7 += f.y;
        f = __half22float2(*(__half2*)&u3.x); a0 += f.x; a1 += f.y;
        f = __half22float2(*(__half2*)&u3.y); a2 += f.x; a3 += f.y;
        f = __half22float2(*(__half2*)&u3.z); a4 += f.x; a5 += f.y;
        f = __half22float2(*(__half2*)&u3.w); a6 += f.x; a7 += f.y;
    }
    for (int i = beg + nChunk * 16 + sub; i < end; i += 4) {
        uint4 u = s1[(size_t)g_rows[i] * 8 + h];
        float2 f;
        f = __half22float2(*(__half2*)&u.x); a0 += f.x; a1 += f.y;
        f = __half22float2(*(__half2*)&u.y); a2 += f.x; a3 += f.y;
        f = __half22float2(*(__half2*)&u.z); a4 += f.x; a5 += f.y;
        f = __half22float2(*(__half2*)&u.w); a6 += f.x; a7 += f.y;
    }
#pragma unroll
    for (int o = 8; o <= 16; o <<= 1) {
        a0 += __shfl_xor_sync(0xffffffffu, a0, o);
        a1 += __shfl_xor_sync(0xffffffffu, a1, o);
        a2 += __shfl_xor_sync(0xffffffffu, a2, o);
        a3 += __shfl_xor_sync(0xffffffffu, a3, o);
        a4 += __shfl_xor_sync(0xffffffffu, a4, o);
        a5 += __shfl_xor_sync(0xffffffffu, a5, o);
        a6 += __shfl_xor_sync(0xffffffffu, a6, o);
        a7 += __shfl_xor_sync(0xffffffffu, a7, o);
    }
    if (sub == 0) {
        uint4 us = s1[(size_t)w * 8 + h];
        float2 f;
        f = __half22float2(*(__half2*)&us.x); a0 += f.x; a1 += f.y;
        f = __half22float2(*(__half2*)&us.y); a2 += f.x; a3 += f.y;
        f = __half22float2(*(__half2*)&us.z); a4 += f.x; a5 += f.y;
        f = __half22float2(*(__half2*)&us.w); a6 += f.x; a7 += f.y;
        float d = g_dinv[w];
        float4 b0 = ((const float4*)b1)[h * 2];
        float4 b2v = ((const float4*)b1)[h * 2 + 1];
        uint4 zz;
        zz.x = pack_h2(fmaxf(fmaf(d, a0, b0.x), 0.f),  fmaxf(fmaf(d, a1, b0.y), 0.f));
        zz.y = pack_h2(fmaxf(fmaf(d, a2, b0.z), 0.f),  fmaxf(fmaf(d, a3, b0.w), 0.f));
        zz.z = pack_h2(fmaxf(fmaf(d, a4, b2v.x), 0.f), fmaxf(fmaf(d, a5, b2v.y), 0.f));
        zz.w = pack_h2(fmaxf(fmaf(d, a6, b2v.z), 0.f), fmaxf(fmaf(d, a7, b2v.w), 0.f));
        ((uint4*)g_z1h)[(size_t)w * 8 + h] = zz;
    }
}

// ------ GEMM2: s2h = fp16( dinv * (z1h @ W2) )   [N,64]x[64,32], z1 in fp16 ------
__global__ __launch_bounds__(256) void k_gemm2(const float* __restrict__ W2, int N) {
    __shared__ float Ws[HDIM * ODIM];
    __shared__ float zs[HDIM * XSTR];
    int t = threadIdx.x;
    for (int i = t; i < HDIM * ODIM; i += 256) Ws[i] = W2[i];

    int node0 = blockIdx.x * 64;
    int lane = t & 31, wrp = t >> 5;
    const unsigned int* z1u = (const unsigned int*)g_z1h;
#pragma unroll
    for (int rep = 0; rep < 8; rep++) {
        int n = wrp * 8 + rep;
        int gn = node0 + n;
        unsigned int u = (gn < N) ? z1u[(size_t)gn * 32 + lane] : 0u;
        float2 f = __half22float2(*(__half2*)&u);
        zs[(2 * lane) * XSTR + n]     = f.x;
        zs[(2 * lane + 1) * XSTR + n] = f.y;
    }
    __syncthreads();

    int n = t & 63;
    int og = t >> 6;
    float acc[8];
#pragma unroll
    for (int i = 0; i < 8; i++) acc[i] = 0.f;
    const float4* Ws4 = (const float4*)Ws;
#pragma unroll 4
    for (int k = 0; k < HDIM; k++) {
        float xv = zs[k * XSTR + n];
        float4 w0 = Ws4[k * 8 + og * 2];
        float4 w1 = Ws4[k * 8 + og * 2 + 1];
        acc[0] = fmaf(xv, w0.x, acc[0]); acc[1] = fmaf(xv, w0.y, acc[1]);
        acc[2] = fmaf(xv, w0.z, acc[2]); acc[3] = fmaf(xv, w0.w, acc[3]);
        acc[4] = fmaf(xv, w1.x, acc[4]); acc[5] = fmaf(xv, w1.y, acc[5]);
        acc[6] = fmaf(xv, w1.z, acc[6]); acc[7] = fmaf(xv, w1.w, acc[7]);
    }
    int gn = node0 + n;
    if (gn < N) {
        float d = g_dinv[gn];
        unsigned int p[4];
#pragma unroll
        for (int j = 0; j < 4; j++) p[j] = pack_h2(d * acc[2 * j], d * acc[2 * j + 1]);
        *(uint4*)(g_s2h + (size_t)gn * ODIM + og * 8) = make_uint4(p[0], p[1], p[2], p[3]);
    }
}

// ---- agg2: 8 lanes x uint2(8B) per 64B row; z2 stored fp16 (uint2 per lane) ----
__global__ __launch_bounds__(256) void k_agg2(const float* __restrict__ b2, int N) {
    int w = (blockIdx.x * blockDim.x + threadIdx.x) >> 5;
    int lane = threadIdx.x & 31;
    if (w >= N) return;
    int h = lane & 7, sub = lane >> 3;
    int beg = g_ptr[w], end = g_ptr[w + 1];
    const uint2* s2 = (const uint2*)g_s2h;

    float a0 = 0.f, a1 = 0.f, a2 = 0.f, a3 = 0.f;
    int nE = end - beg;
    int nChunk = nE >> 4;
    for (int c = 0; c < nChunk; c++) {
        int base = beg + c * 16 + sub;
        int r0 = g_rows[base],     r1 = g_rows[base + 4];
        int r2 = g_rows[base + 8], r3 = g_rows[base + 12];
        uint2 u0 = s2[(size_t)r0 * 8 + h];
        uint2 u1 = s2[(size_t)r1 * 8 + h];
        uint2 u2 = s2[(size_t)r2 * 8 + h];
        uint2 u3 = s2[(size_t)r3 * 8 + h];
        float2 f;
        f = __half22float2(*(__half2*)&u0.x); a0 += f.x; a1 += f.y;
        f = __half22float2(*(__half2*)&u0.y); a2 += f.x; a3 += f.y;
        f = __half22float2(*(__half2*)&u1.x); a0 += f.x; a1 += f.y;
        f = __half22float2(*(__half2*)&u1.y); a2 += f.x; a3 += f.y;
        f = __half22float2(*(__half2*)&u2.x); a0 += f.x; a1 += f.y;
        f = __half22float2(*(__half2*)&u2.y); a2 += f.x; a3 += f.y;
        f = __half22float2(*(__half2*)&u3.x); a0 += f.x; a1 += f.y;
        f = __half22float2(*(__half2*)&u3.y); a2 += f.x; a3 += f.y;
    }
    for (int i = beg + nChunk * 16 + sub; i < end; i += 4) {
        uint2 u = s2[(size_t)g_rows[i] * 8 + h];
        float2 f;
        f = __half22float2(*(__half2*)&u.x); a0 += f.x; a1 += f.y;
        f = __half22float2(*(__half2*)&u.y); a2 += f.x; a3 += f.y;
    }
#pragma unroll
    for (int o = 8; o <= 16; o <<= 1) {
        a0 += __shfl_xor_sync(0xffffffffu, a0, o);
        a1 += __shfl_xor_sync(0xffffffffu, a1, o);
        a2 += __shfl_xor_sync(0xffffffffu, a2, o);
        a3 += __shfl_xor_sync(0xffffffffu, a3, o);
    }
    if (sub == 0) {
        uint2 us = s2[(size_t)w * 8 + h];
        float2 f;
        f = __half22float2(*(__half2*)&us.x); a0 += f.x; a1 += f.y;
        f = __half22float2(*(__half2*)&us.y); a2 += f.x; a3 += f.y;
        float d = g_dinv[w];
        float4 bb = ((const float4*)b2)[h];
        uint2 z;
        z.x = pack_h2(fmaf(d, a0, bb.x), fmaf(d, a1, bb.y));
        z.y = pack_h2(fmaf(d, a2, bb.z), fmaf(d, a3, bb.w));
        ((uint2*)g_z2h)[(size_t)w * 8 + h] = z;
    }
}

// ------ decode: out[p] = dot(z2h[a], z2h[b]) over 32 dims (fp16 gather) ------
__global__ __launch_bounds__(256) void k_decode(const void* __restrict__ eli,
                                                float* __restrict__ out, int EL) {
    int t = blockIdx.x * blockDim.x + threadIdx.x;
    int p = t >> 3;
    int j = t & 7;
    if (p >= EL) return;
    int is32 = g_is32;
    int a = edge_at(eli, p, is32);
    int b = edge_at(eli, (long long)EL + p, is32);
    uint2 ua = ((const uint2*)g_z2h)[(size_t)a * 8 + j];   // 4 halves
    uint2 ub = ((const uint2*)g_z2h)[(size_t)b * 8 + j];
    float2 fa0 = __half22float2(*(__half2*)&ua.x);
    float2 fa1 = __half22float2(*(__half2*)&ua.y);
    float2 fb0 = __half22float2(*(__half2*)&ub.x);
    float2 fb1 = __half22float2(*(__half2*)&ub.y);
    float s = fa0.x * fb0.x + fa0.y * fb0.y + fa1.x * fb1.x + fa1.y * fb1.y;
    s += __shfl_down_sync(0xffffffffu, s, 4, 8);
    s += __shfl_down_sync(0xffffffffu, s, 2, 8);
    s += __shfl_down_sync(0xffffffffu, s, 1, 8);
    if (j == 0) out[p] = s;
}

// ---------------- launch ----------------
extern "C" void kernel_launch(void* const* d_in, const int* in_sizes, int n_in,
                              void* d_out, int out_size) {
    const float* x   = (const float*)d_in[0];
    const float* W1  = (const float*)d_in[1];
    const float* b1  = (const float*)d_in[2];
    const float* W2  = (const float*)d_in[3];
    const float* b2  = (const float*)d_in[4];
    const void*  ei  = d_in[5];
    const void*  eli = d_in[6];

    int H  = in_sizes[2];                 // 64
    int F  = in_sizes[1] / H;             // 128
    int N  = in_sizes[0] / F;             // 100000
    int E  = in_sizes[5] / 2;             // 3200000
    int EL = in_sizes[6] / 2;             // 200000
    float* out = (float*)d_out;

    int NB1024 = (N + 1023) / 1024;
    int EQ = (E + 3) / 4;
    int gemm1_smem = (128 * HPAD + 64 * HPAD) * sizeof(unsigned int);
    cudaFuncSetAttribute(k_gemm1, cudaFuncAttributeMaxDynamicSharedMemorySize, gemm1_smem);

    cudaStream_t s2;
    cudaStreamCreateWithFlags(&s2, cudaStreamNonBlocking);
    cudaEvent_t ev_fork, ev_scan, ev_sc1;
    cudaEventCreateWithFlags(&ev_fork, cudaEventDisableTiming);
    cudaEventCreateWithFlags(&ev_scan, cudaEventDisableTiming);
    cudaEventCreateWithFlags(&ev_sc1, cudaEventDisableTiming);

    // fork: raw gemm1 depends on nothing
    cudaEventRecord(ev_fork, 0);
    cudaStreamWaitEvent(s2, ev_fork, 0);
    k_gemm1<<<(N + 127) / 128, 256, gemm1_smem, s2>>>(x, W1, N);

    // CSR build on main stream
    k_prep<<<(N + 255) / 256, 256>>>(ei, E, N);
    k_count<<<(EQ + 255) / 256, 256>>>(ei, E);
    k_scan<<<NB1024, 1024>>>(N, E);
    cudaEventRecord(ev_scan, 0);

    // side stream: scale1 after scan (overlaps with scatter on main stream)
    cudaStreamWaitEvent(s2, ev_scan, 0);
    k_scale1<<<(N * 4 + 255) / 256, 256, 0, s2>>>(N);
    cudaEventRecord(ev_sc1, s2);

    k_scatter<<<(EQ + 255) / 256, 256>>>(ei, E);
    cudaStreamWaitEvent(0, ev_sc1, 0);

    // serial tail (overlap experiments regressed; keep this structure)
    k_agg1<<<(N + 7) / 8, 256>>>(b1, N);
    k_gemm2<<<(N + 63) / 64, 256>>>(W2, N);
    k_agg2<<<(N + 7) / 8, 256>>>(b2, N);
    k_decode<<<(EL * 8 + 255) / 256, 256>>>(eli, out, EL);

    cudaEventDestroy(ev_fork);
    cudaEventDestroy(ev_scan);
    cudaEventDestroy(ev_sc1);
    cudaStreamDestroy(s2);
}

// round 17
// speedup vs baseline: 1.0673x; 1.0061x over previous
#include <cuda_runtime.h>
#include <cuda_fp16.h>

// ---------------- fixed problem capacities (dataset is fixed) ----------------
#define NMAX 100000
#define EMAX 3200000
#define HDIM 64
#define ODIM 32
#define FDIM 128
#define XSTR 65    // padded fp32 [k][n] stride (gemm2)
#define HPAD 68    // padded half2/uint stride (=136 halves) for tensor gemm smem

// ---------------- device scratch (no allocations allowed) ----------------
__device__ int   g_is32;                              // 1 if edge indices are int32
__device__ int   g_ecnt[NMAX];                        // in-degree (no self loop)
__device__ int   g_ptr[NMAX + 1];                     // CSR offsets
__device__ unsigned long long g_scanstate[128];       // lookback: (flag<<32)|sum
__device__ float g_dinv[NMAX];                        // 1/sqrt(deg+1)
__device__ __align__(16) int     g_rank[EMAX];        // per-edge rank within dst
__device__ __align__(16) int     g_rows[EMAX];        // CSR adjacency: src per slot
__device__ __align__(16) __half2 g_s1h[NMAX * 32];    // fp16 dinv*(x@W1): 64 vals/node
__device__ __align__(16) __half2 g_z1h[NMAX * 32];    // fp16 relu layer-1 output
__device__ __align__(16) __half  g_s2h[NMAX * ODIM];  // fp16 dinv*(z1@W2): 32 vals/node
__device__ __align__(16) __half2 g_z2h[NMAX * 16];    // fp16 layer-2 output

__device__ __forceinline__ int edge_at(const void* p, long long j, int is32) {
    if (is32) return ((const int*)p)[j];
    return (int)((const long long*)p)[j];
}
__device__ __forceinline__ unsigned int pack_h2(float a, float b) {
    __half2 h = __floats2half2_rn(a, b);
    return *reinterpret_cast<unsigned int*>(&h);
}

// ---------------- prep: dtype detect + zero counters/flags ----------------
__global__ void k_prep(const void* ei, int E, int N) {
    int i = blockIdx.x * blockDim.x + threadIdx.x;
    if (i < N) g_ecnt[i] = 0;
    if (i < 128) g_scanstate[i] = 0ull;
    if (blockIdx.x == 0) {
        __shared__ int bad;
        if (threadIdx.x == 0) bad = 0;
        __syncthreads();
        int n = (2 * E < 256) ? 2 * E : 256;
        if (threadIdx.x < n) {
            long long v = ((const long long*)ei)[threadIdx.x];
            if (v < 0 || v >= NMAX) atomicOr(&bad, 1);
        }
        __syncthreads();
        if (threadIdx.x == 0) g_is32 = bad;
    }
}

// ------- count: 4 edges/thread; also records per-edge rank within its dst -------
__global__ void k_count(const void* __restrict__ ei, int E) {
    int q = blockIdx.x * blockDim.x + threadIdx.x;
    int e0 = q * 4;
    if (e0 >= E) return;
    int is32 = g_is32;
    if (e0 + 4 <= E) {
        int4 c;
        if (is32) {
            c = *(const int4*)((const int*)ei + E + e0);
        } else {
            const longlong2* p = (const longlong2*)((const long long*)ei + E + e0);
            longlong2 a = p[0], b = p[1];
            c = make_int4((int)a.x, (int)a.y, (int)b.x, (int)b.y);
        }
        int4 rk;
        rk.x = atomicAdd(&g_ecnt[c.x], 1);
        rk.y = atomicAdd(&g_ecnt[c.y], 1);
        rk.z = atomicAdd(&g_ecnt[c.z], 1);
        rk.w = atomicAdd(&g_ecnt[c.w], 1);
        *(int4*)(g_rank + e0) = rk;
    } else {
        for (int e = e0; e < E; e++) {
            int cc = edge_at(ei, (long long)E + e, is32);
            g_rank[e] = atomicAdd(&g_ecnt[cc], 1);
        }
    }
}

// ---- single-pass exclusive scan: warp scan + warp-parallel decoupled lookback ----
__global__ void k_scan(int N, int E) {
    __shared__ int wsum[32];
    __shared__ int s_prefix;
    int t = threadIdx.x, b = blockIdx.x;
    int lane = t & 31, wid = t >> 5;
    int i = b * 1024 + t;
    int v = (i < N) ? g_ecnt[i] : 0;

    int s = v;
#pragma unroll
    for (int o = 1; o < 32; o <<= 1) {
        int y = __shfl_up_sync(0xffffffffu, s, o);
        if (lane >= o) s += y;
    }
    if (lane == 31) wsum[wid] = s;
    __syncthreads();
    if (wid == 0) {
        int ws = wsum[lane];
#pragma unroll
        for (int o = 1; o < 32; o <<= 1) {
            int y = __shfl_up_sync(0xffffffffu, ws, o);
            if (lane >= o) ws += y;
        }
        wsum[lane] = ws;
    }
    __syncthreads();
    int incl = s + (wid ? wsum[wid - 1] : 0);
    int btotal = wsum[31];

    if (wid == 0) {
        if (b == 0) {
            if (lane == 0) {
                atomicExch(&g_scanstate[0], (2ull << 32) | (unsigned int)btotal);
                s_prefix = 0;
            }
        } else {
            if (lane == 0)
                atomicExch(&g_scanstate[b], (1ull << 32) | (unsigned int)btotal);
            __syncwarp();
            long long pref = 0;
            int base = b;
            while (true) {
                int idx = base - 32 + lane;
                bool valid = idx >= 0;
                unsigned long long st = 0;
                if (valid) {
                    do { st = atomicAdd(&g_scanstate[idx], 0ull); } while ((st >> 32) == 0);
                }
                unsigned m = __ballot_sync(0xffffffffu, valid && (st >> 32) == 2ull);
                int cut = m ? (31 - __clz(m)) : 32;
                bool contrib = valid && (cut == 32 || lane >= cut);
                long long c = contrib ? (long long)(st & 0xffffffffull) : 0;
#pragma unroll
                for (int o = 16; o; o >>= 1) c += __shfl_xor_sync(0xffffffffu, c, o);
                pref += c;
                if (cut != 32) break;
                base -= 32;
            }
            if (lane == 0) {
                atomicExch(&g_scanstate[b],
                           (2ull << 32) | (unsigned int)(pref + (long long)btotal));
                s_prefix = (int)pref;
            }
        }
    }
    __syncthreads();
    int p = s_prefix + incl - v;
    if (i < N) {
        g_ptr[i] = p;
        g_dinv[i] = rsqrtf((float)(g_ecnt[i] + 1));
    }
    if (i == 0) g_ptr[N] = E;
}

// ------- scatter (atomic-free fill): g_rows[ptr[c]+rank] = r -------
__global__ void k_scatter(const void* __restrict__ ei, int E) {
    int q = blockIdx.x * blockDim.x + threadIdx.x;
    int e0 = q * 4;
    if (e0 >= E) return;
    int is32 = g_is32;
    if (e0 + 4 <= E) {
        int4 r, c;
        if (is32) {
            r = *(const int4*)((const int*)ei + e0);
            c = *(const int4*)((const int*)ei + E + e0);
        } else {
            const longlong2* rp = (const longlong2*)((const long long*)ei + e0);
            const longlong2* cp = (const longlong2*)((const long long*)ei + E + e0);
            longlong2 ra = rp[0], rb = rp[1], ca = cp[0], cb = cp[1];
            r = make_int4((int)ra.x, (int)ra.y, (int)rb.x, (int)rb.y);
            c = make_int4((int)ca.x, (int)ca.y, (int)cb.x, (int)cb.y);
        }
        int4 rk = *(const int4*)(g_rank + e0);
        g_rows[g_ptr[c.x] + rk.x] = r.x;
        g_rows[g_ptr[c.y] + rk.y] = r.y;
        g_rows[g_ptr[c.z] + rk.z] = r.z;
        g_rows[g_ptr[c.w] + rk.w] = r.w;
    } else {
        for (int e = e0; e < E; e++) {
            int rr = edge_at(ei, e, is32);
            int cc = edge_at(ei, (long long)E + e, is32);
            g_rows[g_ptr[cc] + g_rank[e]] = rr;
        }
    }
}

// ---------------- GEMM1 (tensor cores): s1h_raw = fp16( x @ W1 ) ----------------
__global__ __launch_bounds__(256) void k_gemm1(const float* __restrict__ x,
                                               const float* __restrict__ W1, int N) {
    extern __shared__ unsigned int smu[];
    unsigned int* xh = smu;
    unsigned int* wh = smu + 128 * HPAD;
    __half* whh = (__half*)wh;
    int t = threadIdx.x;

    for (int i = t; i < FDIM * HDIM; i += 256) {
        int k = i >> 6, n = i & 63;
        whh[n * (2 * HPAD) + k] = __float2half_rn(W1[i]);
    }
    int node0 = blockIdx.x * 128;
    const float4* x4 = (const float4*)x;
    for (int i = t; i < 128 * 32; i += 256) {
        int nd = i >> 5, kq = i & 31;
        int gn = node0 + nd;
        float4 v = (gn < N) ? x4[(size_t)gn * 32 + kq] : make_float4(0.f, 0.f, 0.f, 0.f);
        xh[nd * HPAD + kq * 2]     = pack_h2(v.x, v.y);
        xh[nd * HPAD + kq * 2 + 1] = pack_h2(v.z, v.w);
    }
    __syncthreads();

    int wid = t >> 5, lane = t & 31;
    int g = lane >> 2, tq = lane & 3;
    int nodeW = wid * 16;

    unsigned int A[8][4];
#pragma unroll
    for (int ks = 0; ks < 8; ks++) {
        int base0 = (nodeW + g) * HPAD + ks * 8 + tq;
        int base1 = (nodeW + g + 8) * HPAD + ks * 8 + tq;
        A[ks][0] = xh[base0];
        A[ks][1] = xh[base1];
        A[ks][2] = xh[base0 + 4];
        A[ks][3] = xh[base1 + 4];
    }

    float acc[8][4];
#pragma unroll
    for (int nt = 0; nt < 8; nt++)
#pragma unroll
        for (int j = 0; j < 4; j++) acc[nt][j] = 0.f;

#pragma unroll
    for (int nt = 0; nt < 8; nt++) {
        int brow = (nt * 8 + g) * HPAD + tq;
#pragma unroll
        for (int ks = 0; ks < 8; ks++) {
            unsigned int b0 = wh[brow + ks * 8];
            unsigned int b1 = wh[brow + ks * 8 + 4];
            asm volatile(
                "mma.sync.aligned.m16n8k16.row.col.f32.f16.f16.f32 "
                "{%0,%1,%2,%3}, {%4,%5,%6,%7}, {%8,%9}, {%0,%1,%2,%3};"
                : "+f"(acc[nt][0]), "+f"(acc[nt][1]), "+f"(acc[nt][2]), "+f"(acc[nt][3])
                : "r"(A[ks][0]), "r"(A[ks][1]), "r"(A[ks][2]), "r"(A[ks][3]),
                  "r"(b0), "r"(b1));
        }
    }

    int gn0 = node0 + nodeW + g;
    int gn1 = gn0 + 8;
    unsigned int* s1u = (unsigned int*)g_s1h;
#pragma unroll
    for (int nt = 0; nt < 8; nt++) {
        int ch = (nt * 8 + tq * 2) >> 1;
        if (gn0 < N) s1u[(size_t)gn0 * 32 + ch] = pack_h2(acc[nt][0], acc[nt][1]);
        if (gn1 < N) s1u[(size_t)gn1 * 32 + ch] = pack_h2(acc[nt][2], acc[nt][3]);
    }
}

// ---------------- scale1: s1h *= dinv ----------------
__global__ void k_scale1(int N) {
    int tid = blockIdx.x * blockDim.x + threadIdx.x;
    int node = tid >> 2, q = tid & 3;
    if (node >= N) return;
    float d = g_dinv[node];
    uint4* p = (uint4*)g_s1h + (size_t)node * 8 + q * 2;
#pragma unroll
    for (int u = 0; u < 2; u++) {
        uint4 v = p[u];
        unsigned int* vi = (unsigned int*)&v;
#pragma unroll
        for (int j = 0; j < 4; j++) {
            float2 f = __half22float2(*(__half2*)&vi[j]);
            vi[j] = pack_h2(d * f.x, d * f.y);
        }
        p[u] = v;
    }
}

// ---- agg1: 8 lanes x uint4(16B) per 128B row; 4 edge-parities, 16 edges/iter ----
__global__ __launch_bounds__(256) void k_agg1(const float* __restrict__ b1, int N) {
    int w = (blockIdx.x * blockDim.x + threadIdx.x) >> 5;
    int lane = threadIdx.x & 31;
    if (w >= N) return;
    int h = lane & 7, sub = lane >> 3;
    int beg = g_ptr[w], end = g_ptr[w + 1];
    const uint4* s1 = (const uint4*)g_s1h;

    float a0 = 0.f, a1 = 0.f, a2 = 0.f, a3 = 0.f;
    float a4 = 0.f, a5 = 0.f, a6 = 0.f, a7 = 0.f;
    int nE = end - beg;
    int nChunk = nE >> 4;
    for (int c = 0; c < nChunk; c++) {
        int base = beg + c * 16 + sub;
        int r0 = g_rows[base],     r1 = g_rows[base + 4];
        int r2 = g_rows[base + 8], r3 = g_rows[base + 12];
        uint4 u0 = s1[(size_t)r0 * 8 + h];
        uint4 u1 = s1[(size_t)r1 * 8 + h];
        uint4 u2 = s1[(size_t)r2 * 8 + h];
        uint4 u3 = s1[(size_t)r3 * 8 + h];
        float2 f;
        f = __half22float2(*(__half2*)&u0.x); a0 += f.x; a1 += f.y;
        f = __half22float2(*(__half2*)&u0.y); a2 += f.x; a3 += f.y;
        f = __half22float2(*(__half2*)&u0.z); a4 += f.x; a5 += f.y;
        f = __half22float2(*(__half2*)&u0.w); a6 += f.x; a7 += f.y;
        f = __half22float2(*(__half2*)&u1.x); a0 += f.x; a1 += f.y;
        f = __half22float2(*(__half2*)&u1.y); a2 += f.x; a3 += f.y;
        f = __half22float2(*(__half2*)&u1.z); a4 += f.x; a5 += f.y;
        f = __half22float2(*(__half2*)&u1.w); a6 += f.x; a7 += f.y;
        f = __half22float2(*(__half2*)&u2.x); a0 += f.x; a1 += f.y;
        f = __half22float2(*(__half2*)&u2.y); a2 += f.x; a3 += f.y;
        f = __half22float2(*(__half2*)&u2.z); a4 += f.x; a5 += f.y;
        f = __half22float2(*(__half2*)&u2.w); a6 += f.x; a7 += f.y;
        f = __half22float2(*(__half2*)&u3.x); a0 += f.x; a1 += f.y;
        f = __half22float2(*(__half2*)&u3.y); a2 += f.x; a3 += f.y;
        f = __half22float2(*(__half2*)&u3.z); a4 += f.x; a5 += f.y;
        f = __half22float2(*(__half2*)&u3.w); a6 += f.x; a7 += f.y;
    }
    for (int i = beg + nChunk * 16 + sub; i < end; i += 4) {
        uint4 u = s1[(size_t)g_rows[i] * 8 + h];
        float2 f;
        f = __half22float2(*(__half2*)&u.x); a0 += f.x; a1 += f.y;
        f = __half22float2(*(__half2*)&u.y); a2 += f.x; a3 += f.y;
        f = __half22float2(*(__half2*)&u.z); a4 += f.x; a5 += f.y;
        f = __half22float2(*(__half2*)&u.w); a6 += f.x; a7 += f.y;
    }
#pragma unroll
    for (int o = 8; o <= 16; o <<= 1) {
        a0 += __shfl_xor_sync(0xffffffffu, a0, o);
        a1 += __shfl_xor_sync(0xffffffffu, a1, o);
        a2 += __shfl_xor_sync(0xffffffffu, a2, o);
        a3 += __shfl_xor_sync(0xffffffffu, a3, o);
        a4 += __shfl_xor_sync(0xffffffffu, a4, o);
        a5 += __shfl_xor_sync(0xffffffffu, a5, o);
        a6 += __shfl_xor_sync(0xffffffffu, a6, o);
        a7 += __shfl_xor_sync(0xffffffffu, a7, o);
    }
    if (sub == 0) {
        uint4 us = s1[(size_t)w * 8 + h];
        float2 f;
        f = __half22float2(*(__half2*)&us.x); a0 += f.x; a1 += f.y;
        f = __half22float2(*(__half2*)&us.y); a2 += f.x; a3 += f.y;
        f = __half22float2(*(__half2*)&us.z); a4 += f.x; a5 += f.y;
        f = __half22float2(*(__half2*)&us.w); a6 += f.x; a7 += f.y;
        float d = g_dinv[w];
        float4 b0 = ((const float4*)b1)[h * 2];
        float4 b2v = ((const float4*)b1)[h * 2 + 1];
        uint4 zz;
        zz.x = pack_h2(fmaxf(fmaf(d, a0, b0.x), 0.f),  fmaxf(fmaf(d, a1, b0.y), 0.f));
        zz.y = pack_h2(fmaxf(fmaf(d, a2, b0.z), 0.f),  fmaxf(fmaf(d, a3, b0.w), 0.f));
        zz.z = pack_h2(fmaxf(fmaf(d, a4, b2v.x), 0.f), fmaxf(fmaf(d, a5, b2v.y), 0.f));
        zz.w = pack_h2(fmaxf(fmaf(d, a6, b2v.z), 0.f), fmaxf(fmaf(d, a7, b2v.w), 0.f));
        ((uint4*)g_z1h)[(size_t)w * 8 + h] = zz;
    }
}

// ------ GEMM2: s2h = fp16( dinv * (z1h @ W2) )   [N,64]x[64,32], z1 in fp16 ------
__global__ __launch_bounds__(256) void k_gemm2(const float* __restrict__ W2, int N) {
    __shared__ float Ws[HDIM * ODIM];
    __shared__ float zs[HDIM * XSTR];
    int t = threadIdx.x;
    for (int i = t; i < HDIM * ODIM; i += 256) Ws[i] = W2[i];

    int node0 = blockIdx.x * 64;
    int lane = t & 31, wrp = t >> 5;
    const unsigned int* z1u = (const unsigned int*)g_z1h;
#pragma unroll
    for (int rep = 0; rep < 8; rep++) {
        int n = wrp * 8 + rep;
        int gn = node0 + n;
        unsigned int u = (gn < N) ? z1u[(size_t)gn * 32 + lane] : 0u;
        float2 f = __half22float2(*(__half2*)&u);
        zs[(2 * lane) * XSTR + n]     = f.x;
        zs[(2 * lane + 1) * XSTR + n] = f.y;
    }
    __syncthreads();

    int n = t & 63;
    int og = t >> 6;
    float acc[8];
#pragma unroll
    for (int i = 0; i < 8; i++) acc[i] = 0.f;
    const float4* Ws4 = (const float4*)Ws;
#pragma unroll 4
    for (int k = 0; k < HDIM; k++) {
        float xv = zs[k * XSTR + n];
        float4 w0 = Ws4[k * 8 + og * 2];
        float4 w1 = Ws4[k * 8 + og * 2 + 1];
        acc[0] = fmaf(xv, w0.x, acc[0]); acc[1] = fmaf(xv, w0.y, acc[1]);
        acc[2] = fmaf(xv, w0.z, acc[2]); acc[3] = fmaf(xv, w0.w, acc[3]);
        acc[4] = fmaf(xv, w1.x, acc[4]); acc[5] = fmaf(xv, w1.y, acc[5]);
        acc[6] = fmaf(xv, w1.z, acc[6]); acc[7] = fmaf(xv, w1.w, acc[7]);
    }
    int gn = node0 + n;
    if (gn < N) {
        float d = g_dinv[gn];
        unsigned int p[4];
#pragma unroll
        for (int j = 0; j < 4; j++) p[j] = pack_h2(d * acc[2 * j], d * acc[2 * j + 1]);
        *(uint4*)(g_s2h + (size_t)gn * ODIM + og * 8) = make_uint4(p[0], p[1], p[2], p[3]);
    }
}

// ---- agg2: 8 lanes x uint2(8B) per 64B row; z2 stored fp16 (uint2 per lane) ----
__global__ __launch_bounds__(256) void k_agg2(const float* __restrict__ b2, int N) {
    int w = (blockIdx.x * blockDim.x + threadIdx.x) >> 5;
    int lane = threadIdx.x & 31;
    if (w >= N) return;
    int h = lane & 7, sub = lane >> 3;
    int beg = g_ptr[w], end = g_ptr[w + 1];
    const uint2* s2 = (const uint2*)g_s2h;

    float a0 = 0.f, a1 = 0.f, a2 = 0.f, a3 = 0.f;
    int nE = end - beg;
    int nChunk = nE >> 4;
    for (int c = 0; c < nChunk; c++) {
        int base = beg + c * 16 + sub;
        int r0 = g_rows[base],     r1 = g_rows[base + 4];
        int r2 = g_rows[base + 8], r3 = g_rows[base + 12];
        uint2 u0 = s2[(size_t)r0 * 8 + h];
        uint2 u1 = s2[(size_t)r1 * 8 + h];
        uint2 u2 = s2[(size_t)r2 * 8 + h];
        uint2 u3 = s2[(size_t)r3 * 8 + h];
        float2 f;
        f = __half22float2(*(__half2*)&u0.x); a0 += f.x; a1 += f.y;
        f = __half22float2(*(__half2*)&u0.y); a2 += f.x; a3 += f.y;
        f = __half22float2(*(__half2*)&u1.x); a0 += f.x; a1 += f.y;
        f = __half22float2(*(__half2*)&u1.y); a2 += f.x; a3 += f.y;
        f = __half22float2(*(__half2*)&u2.x); a0 += f.x; a1 += f.y;
        f = __half22float2(*(__half2*)&u2.y); a2 += f.x; a3 += f.y;
        f = __half22float2(*(__half2*)&u3.x); a0 += f.x; a1 += f.y;
        f = __half22float2(*(__half2*)&u3.y); a2 += f.x; a3 += f.y;
    }
    for (int i = beg + nChunk * 16 + sub; i < end; i += 4) {
        uint2 u = s2[(size_t)g_rows[i] * 8 + h];
        float2 f;
        f = __half22float2(*(__half2*)&u.x); a0 += f.x; a1 += f.y;
        f = __half22float2(*(__half2*)&u.y); a2 += f.x; a3 += f.y;
    }
#pragma unroll
    for (int o = 8; o <= 16; o <<= 1) {
        a0 += __shfl_xor_sync(0xffffffffu, a0, o);
        a1 += __shfl_xor_sync(0xffffffffu, a1, o);
        a2 += __shfl_xor_sync(0xffffffffu, a2, o);
        a3 += __shfl_xor_sync(0xffffffffu, a3, o);
    }
    if (sub == 0) {
        uint2 us = s2[(size_t)w * 8 + h];
        float2 f;
        f = __half22float2(*(__half2*)&us.x); a0 += f.x; a1 += f.y;
        f = __half22float2(*(__half2*)&us.y); a2 += f.x; a3 += f.y;
        float d = g_dinv[w];
        float4 bb = ((const float4*)b2)[h];
        uint2 z;
        z.x = pack_h2(fmaf(d, a0, bb.x), fmaf(d, a1, bb.y));
        z.y = pack_h2(fmaf(d, a2, bb.z), fmaf(d, a3, bb.w));
        ((uint2*)g_z2h)[(size_t)w * 8 + h] = z;
    }
}

// ------ decode: out[p] = dot(z2h[a], z2h[b]); 4 lanes/pair, uint4 loads ------
__global__ __launch_bounds__(256) void k_decode(const void* __restrict__ eli,
                                                float* __restrict__ out, int EL) {
    int t = blockIdx.x * blockDim.x + threadIdx.x;
    int p = t >> 2;
    int j = t & 3;
    if (p >= EL) return;
    int is32 = g_is32;
    int a = edge_at(eli, p, is32);
    int b = edge_at(eli, (long long)EL + p, is32);
    uint4 ua = ((const uint4*)g_z2h)[(size_t)a * 4 + j];   // 8 halves
    uint4 ub = ((const uint4*)g_z2h)[(size_t)b * 4 + j];
    float2 fa0 = __half22float2(*(__half2*)&ua.x);
    float2 fa1 = __half22float2(*(__half2*)&ua.y);
    float2 fa2 = __half22float2(*(__half2*)&ua.z);
    float2 fa3 = __half22float2(*(__half2*)&ua.w);
    float2 fb0 = __half22float2(*(__half2*)&ub.x);
    float2 fb1 = __half22float2(*(__half2*)&ub.y);
    float2 fb2 = __half22float2(*(__half2*)&ub.z);
    float2 fb3 = __half22float2(*(__half2*)&ub.w);
    float s = (fa0.x * fb0.x + fa0.y * fb0.y) + (fa1.x * fb1.x + fa1.y * fb1.y)
            + (fa2.x * fb2.x + fa2.y * fb2.y) + (fa3.x * fb3.x + fa3.y * fb3.y);
    s += __shfl_down_sync(0xffffffffu, s, 2, 4);
    s += __shfl_down_sync(0xffffffffu, s, 1, 4);
    if (j == 0) out[p] = s;
}

// ---------------- launch ----------------
extern "C" void kernel_launch(void* const* d_in, const int* in_sizes, int n_in,
                              void* d_out, int out_size) {
    const float* x   = (const float*)d_in[0];
    const float* W1  = (const float*)d_in[1];
    const float* b1  = (const float*)d_in[2];
    const float* W2  = (const float*)d_in[3];
    const float* b2  = (const float*)d_in[4];
    const void*  ei  = d_in[5];
    const void*  eli = d_in[6];

    int H  = in_sizes[2];                 // 64
    int F  = in_sizes[1] / H;             // 128
    int N  = in_sizes[0] / F;             // 100000
    int E  = in_sizes[5] / 2;             // 3200000
    int EL = in_sizes[6] / 2;             // 200000
    float* out = (float*)d_out;

    int NB1024 = (N + 1023) / 1024;
    int EQ = (E + 3) / 4;
    int gemm1_smem = (128 * HPAD + 64 * HPAD) * sizeof(unsigned int);
    cudaFuncSetAttribute(k_gemm1, cudaFuncAttributeMaxDynamicSharedMemorySize, gemm1_smem);

    cudaStream_t s2;
    cudaStreamCreateWithFlags(&s2, cudaStreamNonBlocking);
    cudaEvent_t ev_fork, ev_scan, ev_sc1;
    cudaEventCreateWithFlags(&ev_fork, cudaEventDisableTiming);
    cudaEventCreateWithFlags(&ev_scan, cudaEventDisableTiming);
    cudaEventCreateWithFlags(&ev_sc1, cudaEventDisableTiming);

    // fork: raw gemm1 depends on nothing
    cudaEventRecord(ev_fork, 0);
    cudaStreamWaitEvent(s2, ev_fork, 0);
    k_gemm1<<<(N + 127) / 128, 256, gemm1_smem, s2>>>(x, W1, N);

    // CSR build on main stream
    k_prep<<<(N + 255) / 256, 256>>>(ei, E, N);
    k_count<<<(EQ + 255) / 256, 256>>>(ei, E);
    k_scan<<<NB1024, 1024>>>(N, E);
    cudaEventRecord(ev_scan, 0);

    // side stream: scale1 after scan (overlaps with scatter on main stream)
    cudaStreamWaitEvent(s2, ev_scan, 0);
    k_scale1<<<(N * 4 + 255) / 256, 256, 0, s2>>>(N);
    cudaEventRecord(ev_sc1, s2);

    k_scatter<<<(EQ + 255) / 256, 256>>>(ei, E);
    cudaStreamWaitEvent(0, ev_sc1, 0);

    // serial tail (overlap experiments regressed; keep this structure)
    k_agg1<<<(N + 7) / 8, 256>>>(b1, N);
    k_gemm2<<<(N + 63) / 64, 256>>>(W2, N);
    k_agg2<<<(N + 7) / 8, 256>>>(b2, N);
    k_decode<<<(EL * 4 + 255) / 256, 256>>>(eli, out, EL);

    cudaEventDestroy(ev_fork);
    cudaEventDestroy(ev_scan);
    cudaEventDestroy(ev_sc1);
    cudaStreamDestroy(s2);
}